// round 4
// baseline (speedup 1.0000x reference)
#include <cuda_runtime.h>
#include <cuda_fp16.h>
#include <stdint.h>

#define TT 256
#define BB 128
#define VV 256
#define EE 512
#define NH 1024
#define TB (TT*BB)          // 32768
#define G4 (4*NH)           // 4096

// ---------------- static device scratch ----------------
__device__ __align__(16) __half g_inph[(size_t)TB*VV];
__device__ __align__(16) __half g_embs[(size_t)TB*EE];
__device__ __align__(16) float  g_X[(size_t)TB*G4];
__device__ __align__(16) __half g_H0[(size_t)TB*NH];
__device__ __align__(16) __half g_H1[(size_t)TB*NH];
__device__ __align__(16) __half g_embT[EE*VV];           // [512][256]
__device__ __align__(16) __half g_w0xT[(size_t)G4*EE];   // [4096][512]
__device__ __align__(16) __half g_w0hT[(size_t)G4*NH];   // [4096][1024]
__device__ __align__(16) __half g_w1xT[(size_t)G4*NH];   // [4096][1024]
__device__ __align__(16) __half g_w1hT[(size_t)G4*NH];   // [4096][1024]
__device__ __align__(16) __half g_owT[VV*NH];            // [256][1024]
__device__ int g_flags[2][128];

// ---------------- helpers ----------------
__device__ __forceinline__ void mma16(float d[4], const unsigned a[4], const unsigned b[2]) {
    asm volatile(
        "mma.sync.aligned.m16n8k16.row.col.f32.f16.f16.f32 "
        "{%0,%1,%2,%3}, {%4,%5,%6,%7}, {%8,%9}, {%0,%1,%2,%3};\n"
        : "+f"(d[0]), "+f"(d[1]), "+f"(d[2]), "+f"(d[3])
        : "r"(a[0]), "r"(a[1]), "r"(a[2]), "r"(a[3]), "r"(b[0]), "r"(b[1]));
}
__device__ __forceinline__ void ldsm_x4(unsigned r[4], const __half* p) {
    unsigned a = (unsigned)__cvta_generic_to_shared(p);
    asm volatile("ldmatrix.sync.aligned.m8n8.x4.shared.b16 {%0,%1,%2,%3}, [%4];\n"
        : "=r"(r[0]), "=r"(r[1]), "=r"(r[2]), "=r"(r[3]) : "r"(a));
}
__device__ __forceinline__ void cpa16(__half* dst, const __half* src) {
    unsigned d = (unsigned)__cvta_generic_to_shared(dst);
    asm volatile("cp.async.cg.shared.global [%0], [%1], 16;\n" :: "r"(d), "l"(src));
}
#define CPA_COMMIT() asm volatile("cp.async.commit_group;\n" ::: "memory")
template <int N> __device__ __forceinline__ void cpa_wait() {
    asm volatile("cp.async.wait_group %0;\n" :: "n"(N) : "memory");
}
__device__ __forceinline__ int ldacq(const int* p) {
    int v;
    asm volatile("ld.acquire.gpu.global.b32 %0, [%1];" : "=r"(v) : "l"(p) : "memory");
    return v;
}
__device__ __forceinline__ void cstore(__half* C, size_t i, float v) { C[i] = __float2half(v); }
__device__ __forceinline__ void cstore(float*  C, size_t i, float v) { C[i] = v; }
__device__ __forceinline__ float sigf(float x) { return 1.f / (1.f + __expf(-x)); }

__global__ void zero_flags() {
    if (threadIdx.x < 128) {
        g_flags[0][threadIdx.x] = 0;
        g_flags[1][threadIdx.x] = 0;
    }
}
__global__ void f2h_kernel(const float* __restrict__ s, __half* __restrict__ d, int n) {
    for (int i = blockIdx.x * blockDim.x + threadIdx.x; i < n; i += gridDim.x * blockDim.x)
        d[i] = __float2half(s[i]);
}
// src fp32 [K][N] (row stride lds) -> dst fp16 [N][K]
__global__ void transpose_cvt(const float* __restrict__ src, int lds,
                              __half* __restrict__ dst, int K, int N) {
    __shared__ float tile[32][33];
    int kb = blockIdx.x * 32, nb = blockIdx.y * 32;
    #pragma unroll
    for (int i = threadIdx.y; i < 32; i += 8) {
        int k = kb + i, n = nb + threadIdx.x;
        tile[i][threadIdx.x] = (k < K && n < N) ? src[(size_t)k * lds + n] : 0.f;
    }
    __syncthreads();
    #pragma unroll
    for (int i = threadIdx.y; i < 32; i += 8) {
        int n = nb + i, k = kb + threadIdx.x;
        if (n < N && k < K) dst[(size_t)n * K + k] = __float2half(tile[threadIdx.x][i]);
    }
}

// ---------------- generic fp16 GEMM: C[M,N] = A[M,K] @ Bt[N,K]^T (+bias) ----------------
#define GAST (128*40)
#define GBST (64*40)
#define GEMM_SMEM ((4*(GAST+GBST))*2)

template <typename TOUT>
__global__ void __launch_bounds__(256) gemm16(
    const __half* __restrict__ A, int lda,
    const __half* __restrict__ Bt,
    TOUT* __restrict__ C, int ldc,
    const float* __restrict__ bias,
    int M, int N, int K)
{
    extern __shared__ __half sm[];
    __half* As = sm;
    __half* Bs = sm + 4*GAST;

    const int tid = threadIdx.x;
    const int bm = blockIdx.y * 128, bn = blockIdx.x * 64;
    const int wid = tid >> 5, lane = tid & 31;
    const int wr = (wid >> 1) * 32, wc = (wid & 1) * 32;
    const int r = lane >> 2, cl = lane & 3;

    float acc[2][4][4];
    #pragma unroll
    for (int i = 0; i < 2; ++i)
        #pragma unroll
        for (int j = 0; j < 4; ++j)
            #pragma unroll
            for (int k = 0; k < 4; ++k) acc[i][j][k] = 0.f;

    auto loadG = [&](int s, int kt) {
        #pragma unroll
        for (int i = 0; i < 2; ++i) {
            int idx = tid + i * 256;
            int row = idx >> 2, cc = idx & 3;
            cpa16(As + s*GAST + row*40 + cc*8,
                  A + (size_t)(bm + row) * lda + kt*32 + cc*8);
        }
        {
            int row = tid >> 2, cc = tid & 3;
            cpa16(Bs + s*GBST + row*40 + cc*8,
                  Bt + (size_t)(bn + row) * K + kt*32 + cc*8);
        }
    };

    const int ktiles = K >> 5;
    #pragma unroll
    for (int s = 0; s < 3; ++s) { if (s < ktiles) loadG(s, s); CPA_COMMIT(); }

    // ldmatrix lane address components
    const int a_row = (lane & 15);
    const int a_col = (lane >> 4) << 3;
    const int b_row = (lane & 7) + ((lane >> 4) << 3);
    const int b_col = (lane & 8);

    for (int kt = 0; kt < ktiles; ++kt) {
        cpa_wait<2>();
        __syncthreads();
        if (kt + 3 < ktiles) loadG((kt + 3) & 3, kt + 3);
        CPA_COMMIT();

        const __half* sA = As + (kt & 3) * GAST;
        const __half* sB = Bs + (kt & 3) * GBST;
        #pragma unroll
        for (int ks = 0; ks < 2; ++ks) {
            const int k0 = ks * 16;
            unsigned af[2][4], bf01[4], bf23[4];
            #pragma unroll
            for (int mt = 0; mt < 2; ++mt)
                ldsm_x4(af[mt], sA + (wr + mt*16 + a_row)*40 + k0 + a_col);
            ldsm_x4(bf01, sB + (wc      + b_row)*40 + k0 + b_col);
            ldsm_x4(bf23, sB + (wc + 16 + b_row)*40 + k0 + b_col);
            #pragma unroll
            for (int mt = 0; mt < 2; ++mt) {
                mma16(acc[mt][0], af[mt], bf01 + 0);
                mma16(acc[mt][1], af[mt], bf01 + 2);
                mma16(acc[mt][2], af[mt], bf23 + 0);
                mma16(acc[mt][3], af[mt], bf23 + 2);
            }
        }
    }

    #pragma unroll
    for (int mt = 0; mt < 2; ++mt)
        #pragma unroll
        for (int nt = 0; nt < 4; ++nt) {
            const int row = bm + wr + mt*16 + r;
            const int col = bn + wc + nt*8 + 2*cl;
            const float b0 = bias ? bias[col]     : 0.f;
            const float b1 = bias ? bias[col + 1] : 0.f;
            cstore(C, (size_t)row * ldc + col,           acc[mt][nt][0] + b0);
            cstore(C, (size_t)row * ldc + col + 1,       acc[mt][nt][1] + b1);
            cstore(C, (size_t)(row + 8) * ldc + col,     acc[mt][nt][2] + b0);
            cstore(C, (size_t)(row + 8) * ldc + col + 1, acc[mt][nt][3] + b1);
        }
}

// ---------------- persistent LSTM layer kernel ----------------
// 128 CTAs (1/SM). CTA bx owns hidden cols [bx*8, bx*8+8) of all 4 gates
// (GEMM N=32 = 4 gates x 8 cols, K=1024). W_h slice (64KB) resident in smem.
// 4 mma warps (32x32 warp tiles); warps 4-7 only feed cp.async.
// Inter-CTA sync: per-CTA completion flags, chunk-wise polling (wavefront).
#define AST (128*72)
#define LSTM_SMEM ((32*1032 + 4*AST)*2)

__global__ void __launch_bounds__(256, 1) lstm_layer(
    const __half* __restrict__ WhT,    // [4096][1024]
    const float*  __restrict__ X,      // [T*128][4096]
    __half* __restrict__ H,            // [T*128][1024]
    int* __restrict__ flags)           // [128]
{
    extern __shared__ __half sm[];
    __half* Bs = sm;                   // 32 x 1032 (n = gate*8+j, k = 0..1023)
    __half* As = sm + 32*1032;         // 4 stages x 128 x 72

    const int tid = threadIdx.x, lane = tid & 31, wid = tid >> 5;
    const int r = lane >> 2, cl = lane & 3;
    const int bx = blockIdx.x;
    const int wr = wid * 32;           // mma warp row base (wid<4)
    const int colg = bx * 8 + 2 * cl;
    const int fidx = tid & 7;

    // ldmatrix lane address components
    const int a_row = (lane & 15);
    const int a_col = (lane >> 4) << 3;
    const int b_row = (lane & 7) + ((lane >> 4) << 3);
    const int b_col = (lane & 8);

    // load W_h slice once: rows g*1024 + bx*8 + j  ->  Bs[g*8+j][0..1023]
    #pragma unroll
    for (int i = 0; i < 16; ++i) {
        int idx = tid + i * 256;            // 0..4095
        int n = idx >> 7, cc = idx & 127;
        int g = n >> 3, j = n & 7;
        cpa16(Bs + n*1032 + cc*8,
              WhT + (size_t)(g*1024 + bx*8 + j) * 1024 + cc*8);
    }
    CPA_COMMIT();
    cpa_wait<0>();
    __syncthreads();

    float cc8[8];
    #pragma unroll
    for (int i = 0; i < 8; ++i) cc8[i] = 0.f;

    auto loadA = [&](__half* dst, const __half* hsrc, int kt) {
        #pragma unroll
        for (int i = 0; i < 4; ++i) {
            int idx = tid + i * 256;        // 0..1023
            int row = idx >> 3, ccc = idx & 7;
            cpa16(dst + row*72 + ccc*8, hsrc + (size_t)row*1024 + kt*64 + ccc*8);
        }
    };

    for (int t = 0; t < TT; ++t) {
        // prefetch X gate values (independent of h) into registers
        float2 xv[2][2][4];
        if (wid < 4) {
            const float* Xt = X + (size_t)t * BB * G4;
            #pragma unroll
            for (int mt = 0; mt < 2; ++mt)
                #pragma unroll
                for (int e = 0; e < 2; ++e) {
                    int row = wr + mt*16 + r + e*8;
                    const float* xb = Xt + (size_t)row * 4096 + colg;
                    #pragma unroll
                    for (int g = 0; g < 4; ++g)
                        xv[mt][e][g] = *(const float2*)(xb + g * 1024);
                }
        }

        float acc[2][4][4];
        #pragma unroll
        for (int i = 0; i < 2; ++i)
            #pragma unroll
            for (int j = 0; j < 4; ++j)
                #pragma unroll
                for (int k = 0; k < 4; ++k) acc[i][j][k] = 0.f;

        if (t > 0) {
            const __half* hsrc = H + (size_t)(t - 1) * BB * NH;

            // prologue: poll chunks 0..2, load stages
            int v0 = ldacq(flags + 0*8 + fidx);
            int v1 = ldacq(flags + 1*8 + fidx);
            int v2 = ldacq(flags + 2*8 + fidx);
            while (v0 < t) v0 = ldacq(flags + 0*8 + fidx);
            loadA(As + 0*AST, hsrc, 0); CPA_COMMIT();
            while (v1 < t) v1 = ldacq(flags + 1*8 + fidx);
            loadA(As + 1*AST, hsrc, 1); CPA_COMMIT();
            while (v2 < t) v2 = ldacq(flags + 2*8 + fidx);
            loadA(As + 2*AST, hsrc, 2); CPA_COMMIT();

            int fv = ldacq(flags + 3*8 + fidx);

            #pragma unroll 1
            for (int kt = 0; kt < 16; ++kt) {
                if (kt + 3 < 16) { while (fv < t) fv = ldacq(flags + (kt+3)*8 + fidx); }
                cpa_wait<2>();
                __syncthreads();
                if (kt + 3 < 16) loadA(As + ((kt + 3) & 3) * AST, hsrc, kt + 3);
                CPA_COMMIT();
                if (kt + 4 < 16) fv = ldacq(flags + (kt+4)*8 + fidx);

                if (wid < 4) {
                    const __half* sA = As + (kt & 3) * AST;
                    const __half* sBk = Bs + kt * 64;
                    #pragma unroll
                    for (int ks = 0; ks < 4; ++ks) {
                        const int k0 = ks * 16;
                        unsigned af[2][4], bf01[4], bf23[4];
                        ldsm_x4(af[0], sA + (wr      + a_row)*72 + k0 + a_col);
                        ldsm_x4(af[1], sA + (wr + 16 + a_row)*72 + k0 + a_col);
                        ldsm_x4(bf01, sBk + (size_t)(b_row     )*1032 + k0 + b_col);
                        ldsm_x4(bf23, sBk + (size_t)(b_row + 16)*1032 + k0 + b_col);
                        #pragma unroll
                        for (int mt = 0; mt < 2; ++mt) {
                            mma16(acc[mt][0], af[mt], bf01 + 0);
                            mma16(acc[mt][1], af[mt], bf01 + 2);
                            mma16(acc[mt][2], af[mt], bf23 + 0);
                            mma16(acc[mt][3], af[mt], bf23 + 2);
                        }
                    }
                }
            }
        }

        // gates + state update in registers (mma warps only)
        if (wid < 4) {
            #pragma unroll
            for (int mt = 0; mt < 2; ++mt)
                #pragma unroll
                for (int e = 0; e < 2; ++e) {
                    const int row = wr + mt*16 + r + e*8;
                    const int q = 2 * e;
                    const float lf0 = acc[mt][0][q]   + xv[mt][e][0].x;
                    const float lf1 = acc[mt][0][q+1] + xv[mt][e][0].y;
                    const float li0 = acc[mt][1][q]   + xv[mt][e][1].x;
                    const float li1 = acc[mt][1][q+1] + xv[mt][e][1].y;
                    const float lo0 = acc[mt][2][q]   + xv[mt][e][2].x;
                    const float lo1 = acc[mt][2][q+1] + xv[mt][e][2].y;
                    const float lg0 = acc[mt][3][q]   + xv[mt][e][3].x;
                    const float lg1 = acc[mt][3][q+1] + xv[mt][e][3].y;
                    const int ci = (mt*2 + e) * 2;
                    const float c0 = sigf(lf0) * cc8[ci]   + sigf(li0) * tanhf(lg0);
                    const float c1 = sigf(lf1) * cc8[ci+1] + sigf(li1) * tanhf(lg1);
                    cc8[ci] = c0; cc8[ci+1] = c1;
                    const float h0 = sigf(lo0) * tanhf(c0);
                    const float h1 = sigf(lo1) * tanhf(c1);
                    *(__half2*)&H[(size_t)t*BB*NH + (size_t)row*1024 + colg] =
                        __floats2half2_rn(h0, h1);
                }
        }

        __syncthreads();   // all H stores of this CTA done (cta-visible to tid 0)
        if (tid == 0 && t + 1 < TT) {
            asm volatile("st.release.gpu.global.b32 [%0], %1;"
                         :: "l"(flags + bx), "r"(t + 1) : "memory");
        }
    }
}

// ---------------- launch ----------------
extern "C" void kernel_launch(void* const* d_in, const int* in_sizes, int n_in,
                              void* d_out, int out_size) {
    (void)in_sizes; (void)n_in; (void)out_size;
    const float* inputs = (const float*)d_in[0];
    const float* emb    = (const float*)d_in[1];
    const float* w0     = (const float*)d_in[2];
    const float* b0     = (const float*)d_in[3];
    const float* w1     = (const float*)d_in[4];
    const float* b1     = (const float*)d_in[5];
    const float* outw   = (const float*)d_in[6];
    const float* outb   = (const float*)d_in[7];
    float* out = (float*)d_out;

    __half *inph, *embs, *H0, *H1, *embT, *w0xT, *w0hT, *w1xT, *w1hT, *owT;
    float *X;
    int *flg;
    cudaGetSymbolAddress((void**)&inph, g_inph);
    cudaGetSymbolAddress((void**)&embs, g_embs);
    cudaGetSymbolAddress((void**)&X,    g_X);
    cudaGetSymbolAddress((void**)&H0,   g_H0);
    cudaGetSymbolAddress((void**)&H1,   g_H1);
    cudaGetSymbolAddress((void**)&embT, g_embT);
    cudaGetSymbolAddress((void**)&w0xT, g_w0xT);
    cudaGetSymbolAddress((void**)&w0hT, g_w0hT);
    cudaGetSymbolAddress((void**)&w1xT, g_w1xT);
    cudaGetSymbolAddress((void**)&w1hT, g_w1hT);
    cudaGetSymbolAddress((void**)&owT,  g_owT);
    cudaGetSymbolAddress((void**)&flg,  g_flags);

    cudaFuncSetAttribute(lstm_layer,     cudaFuncAttributeMaxDynamicSharedMemorySize, LSTM_SMEM);
    cudaFuncSetAttribute(gemm16<float>,  cudaFuncAttributeMaxDynamicSharedMemorySize, GEMM_SMEM);
    cudaFuncSetAttribute(gemm16<__half>, cudaFuncAttributeMaxDynamicSharedMemorySize, GEMM_SMEM);

    // prep
    f2h_kernel<<<1024, 256>>>(inputs, inph, TB * VV);
    {
        dim3 blk(32, 8);
        transpose_cvt<<<dim3(VV/32, EE/32), blk>>>(emb,                EE, embT, VV, EE);
        transpose_cvt<<<dim3(EE/32, G4/32), blk>>>(w0,                 G4, w0xT, EE, G4);
        transpose_cvt<<<dim3(NH/32, G4/32), blk>>>(w0 + (size_t)EE*G4, G4, w0hT, NH, G4);
        transpose_cvt<<<dim3(NH/32, G4/32), blk>>>(w1,                 G4, w1xT, NH, G4);
        transpose_cvt<<<dim3(NH/32, G4/32), blk>>>(w1 + (size_t)NH*G4, G4, w1hT, NH, G4);
        transpose_cvt<<<dim3(NH/32, VV/32), blk>>>(outw,               VV, owT,  NH, VV);
    }
    zero_flags<<<1, 128>>>();

    // embs = inputs @ emb
    gemm16<__half><<<dim3(EE/64, TB/128), 256, GEMM_SMEM>>>(inph, VV, embT, embs, EE, nullptr, TB, EE, VV);
    // X = embs @ W0x + b0
    gemm16<float><<<dim3(G4/64, TB/128), 256, GEMM_SMEM>>>(embs, EE, w0xT, X, G4, b0, TB, G4, EE);
    // layer 0 (persistent, wavefront-synced)
    lstm_layer<<<128, 256, LSTM_SMEM>>>(w0hT, X, H0, flg);
    // X = H0 @ W1x + b1
    gemm16<float><<<dim3(G4/64, TB/128), 256, GEMM_SMEM>>>(H0, NH, w1xT, X, G4, b1, TB, G4, NH);
    // layer 1 (persistent, wavefront-synced)
    lstm_layer<<<128, 256, LSTM_SMEM>>>(w1hT, X, H1, flg + 128);
    // logits = H1 @ out_w + out_b
    gemm16<float><<<dim3(VV/64, TB/128), 256, GEMM_SMEM>>>(H1, NH, owT, out, VV, outb, TB, VV, NH);
}

// round 5
// speedup vs baseline: 1.1387x; 1.1387x over previous
#include <cuda_runtime.h>
#include <cuda_fp16.h>
#include <stdint.h>

#define TT 256
#define BB 128
#define VV 256
#define EE 512
#define NH 1024
#define TB (TT*BB)          // 32768
#define G4 (4*NH)           // 4096

// ---------------- static device scratch ----------------
__device__ __align__(16) __half g_inph[(size_t)TB*VV];
__device__ __align__(16) __half g_embs[(size_t)TB*EE];
__device__ __align__(16) float  g_X[(size_t)TB*G4];
__device__ __align__(16) __half g_H0[(size_t)TB*NH];
__device__ __align__(16) __half g_H1[(size_t)TB*NH];
__device__ __align__(16) __half g_embT[EE*VV];           // [512][256]
__device__ __align__(16) __half g_w0xT[(size_t)G4*EE];   // [4096][512]
__device__ __align__(16) __half g_w0hT[(size_t)G4*NH];   // [4096][1024]
__device__ __align__(16) __half g_w1xT[(size_t)G4*NH];   // [4096][1024]
__device__ __align__(16) __half g_w1hT[(size_t)G4*NH];   // [4096][1024]
__device__ __align__(16) __half g_owT[VV*NH];            // [256][1024]
__device__ int g_flags[2][128];

// ---------------- helpers ----------------
__device__ __forceinline__ void mma16(float d[4], const unsigned a[4], const unsigned b[2]) {
    asm volatile(
        "mma.sync.aligned.m16n8k16.row.col.f32.f16.f16.f32 "
        "{%0,%1,%2,%3}, {%4,%5,%6,%7}, {%8,%9}, {%0,%1,%2,%3};\n"
        : "+f"(d[0]), "+f"(d[1]), "+f"(d[2]), "+f"(d[3])
        : "r"(a[0]), "r"(a[1]), "r"(a[2]), "r"(a[3]), "r"(b[0]), "r"(b[1]));
}
__device__ __forceinline__ void ldsm_x4(unsigned r[4], const __half* p) {
    unsigned a = (unsigned)__cvta_generic_to_shared(p);
    asm volatile("ldmatrix.sync.aligned.m8n8.x4.shared.b16 {%0,%1,%2,%3}, [%4];\n"
        : "=r"(r[0]), "=r"(r[1]), "=r"(r[2]), "=r"(r[3]) : "r"(a));
}
__device__ __forceinline__ void cpa16(__half* dst, const __half* src) {
    unsigned d = (unsigned)__cvta_generic_to_shared(dst);
    asm volatile("cp.async.cg.shared.global [%0], [%1], 16;\n" :: "r"(d), "l"(src));
}
#define CPA_COMMIT() asm volatile("cp.async.commit_group;\n" ::: "memory")
template <int N> __device__ __forceinline__ void cpa_wait() {
    asm volatile("cp.async.wait_group %0;\n" :: "n"(N) : "memory");
}
__device__ __forceinline__ int ldacq(const int* p) {
    int v;
    asm volatile("ld.acquire.gpu.global.b32 %0, [%1];" : "=r"(v) : "l"(p) : "memory");
    return v;
}
__device__ __forceinline__ void cstore2(float* C, size_t i, float a, float b) {
    *(float2*)&C[i] = make_float2(a, b);
}
__device__ __forceinline__ void cstore2(__half* C, size_t i, float a, float b) {
    *(__half2*)&C[i] = __floats2half2_rn(a, b);
}
__device__ __forceinline__ float sigf(float x) { return 1.f / (1.f + __expf(-x)); }

__global__ void zero_flags() {
    if (threadIdx.x < 128) {
        g_flags[0][threadIdx.x] = 0;
        g_flags[1][threadIdx.x] = 0;
    }
}
__global__ void f2h_kernel(const float* __restrict__ s, __half* __restrict__ d, int n) {
    for (int i = blockIdx.x * blockDim.x + threadIdx.x; i < n; i += gridDim.x * blockDim.x)
        d[i] = __float2half(s[i]);
}
// src fp32 [K][N] (row stride lds) -> dst fp16 [N][K]
__global__ void transpose_cvt(const float* __restrict__ src, int lds,
                              __half* __restrict__ dst, int K, int N) {
    __shared__ float tile[32][33];
    int kb = blockIdx.x * 32, nb = blockIdx.y * 32;
    #pragma unroll
    for (int i = threadIdx.y; i < 32; i += 8) {
        int k = kb + i, n = nb + threadIdx.x;
        tile[i][threadIdx.x] = (k < K && n < N) ? src[(size_t)k * lds + n] : 0.f;
    }
    __syncthreads();
    #pragma unroll
    for (int i = threadIdx.y; i < 32; i += 8) {
        int n = nb + i, k = kb + threadIdx.x;
        if (n < N && k < K) dst[(size_t)n * K + k] = __float2half(tile[threadIdx.x][i]);
    }
}

// ---------------- fp16 GEMM: C[M,N] = A[M,K] @ Bt[N,K]^T (+bias) ----------------
// CTA tile 128x128, K-tile 32, 4-stage cp.async, 256 thr (8 warps, 2x4), warp 64x32.
#define GAST (128*40)
#define GBST (128*40)
#define GEMM_SMEM ((4*(GAST+GBST))*2)

template <typename TOUT>
__global__ void __launch_bounds__(256, 2) gemm16(
    const __half* __restrict__ A, int lda,
    const __half* __restrict__ Bt,
    TOUT* __restrict__ C, int ldc,
    const float* __restrict__ bias,
    int M, int N, int K)
{
    extern __shared__ __half sm[];
    __half* As = sm;
    __half* Bs = sm + 4*GAST;

    const int tid = threadIdx.x;
    const int bm = blockIdx.y * 128, bn = blockIdx.x * 128;
    const int wid = tid >> 5, lane = tid & 31;
    const int wr = (wid & 1) * 64, wc = (wid >> 1) * 32;
    const int r = lane >> 2, cl = lane & 3;

    float acc[4][4][4];
    #pragma unroll
    for (int i = 0; i < 4; ++i)
        #pragma unroll
        for (int j = 0; j < 4; ++j)
            #pragma unroll
            for (int k = 0; k < 4; ++k) acc[i][j][k] = 0.f;

    auto loadG = [&](int s, int kt) {
        #pragma unroll
        for (int i = 0; i < 2; ++i) {
            int idx = tid + i * 256;
            int row = idx >> 2, cc = idx & 3;
            cpa16(As + s*GAST + row*40 + cc*8,
                  A + (size_t)(bm + row) * lda + kt*32 + cc*8);
            cpa16(Bs + s*GBST + row*40 + cc*8,
                  Bt + (size_t)(bn + row) * K + kt*32 + cc*8);
        }
    };

    const int ktiles = K >> 5;
    #pragma unroll
    for (int s = 0; s < 3; ++s) { if (s < ktiles) loadG(s, s); CPA_COMMIT(); }

    // ldmatrix lane address components
    const int a_row = (lane & 15);
    const int a_col = (lane >> 4) << 3;
    const int b_row = (lane & 7) + ((lane >> 4) << 3);
    const int b_col = (lane & 8);

    for (int kt = 0; kt < ktiles; ++kt) {
        cpa_wait<2>();
        __syncthreads();
        if (kt + 3 < ktiles) loadG((kt + 3) & 3, kt + 3);
        CPA_COMMIT();

        const __half* sA = As + (kt & 3) * GAST;
        const __half* sB = Bs + (kt & 3) * GBST;
        #pragma unroll
        for (int ks = 0; ks < 2; ++ks) {
            const int k0 = ks * 16;
            unsigned af[4][4], bf01[4], bf23[4];
            #pragma unroll
            for (int mt = 0; mt < 4; ++mt)
                ldsm_x4(af[mt], sA + (wr + mt*16 + a_row)*40 + k0 + a_col);
            ldsm_x4(bf01, sB + (wc      + b_row)*40 + k0 + b_col);
            ldsm_x4(bf23, sB + (wc + 16 + b_row)*40 + k0 + b_col);
            #pragma unroll
            for (int mt = 0; mt < 4; ++mt) {
                mma16(acc[mt][0], af[mt], bf01 + 0);
                mma16(acc[mt][1], af[mt], bf01 + 2);
                mma16(acc[mt][2], af[mt], bf23 + 0);
                mma16(acc[mt][3], af[mt], bf23 + 2);
            }
        }
    }

    #pragma unroll
    for (int mt = 0; mt < 4; ++mt)
        #pragma unroll
        for (int nt = 0; nt < 4; ++nt) {
            const int row = bm + wr + mt*16 + r;
            const int col = bn + wc + nt*8 + 2*cl;
            const float b0 = bias ? bias[col]     : 0.f;
            const float b1 = bias ? bias[col + 1] : 0.f;
            cstore2(C, (size_t)row * ldc + col,       acc[mt][nt][0] + b0, acc[mt][nt][1] + b1);
            cstore2(C, (size_t)(row + 8) * ldc + col, acc[mt][nt][2] + b0, acc[mt][nt][3] + b1);
        }
}

// ---------------- persistent LSTM layer kernel ----------------
// 128 CTAs (1/SM). CTA bx owns hidden cols [bx*8, bx*8+8) of all 4 gates
// (GEMM N=32 = 4 gates x 8 cols, K=1024). W_h slice (64KB) resident in smem.
// 4 mma warps (32x32 warp tiles); warps 4-7 feed cp.async; warp 4 polls flags.
// Sync: ONE poll per step (warp 4: 32 lanes x 4 flags), producers st.release.
#define AST (128*72)
#define LSTM_SMEM ((32*1032 + 4*AST)*2)

__global__ void __launch_bounds__(256, 1) lstm_layer(
    const __half* __restrict__ WhT,    // [4096][1024]
    const float*  __restrict__ X,      // [T*128][4096]
    __half* __restrict__ H,            // [T*128][1024]
    int* __restrict__ flags)           // [128]
{
    extern __shared__ __half sm[];
    __half* Bs = sm;                   // 32 x 1032 (n = gate*8+j, k = 0..1023)
    __half* As = sm + 32*1032;         // 4 stages x 128 x 72

    const int tid = threadIdx.x, lane = tid & 31, wid = tid >> 5;
    const int r = lane >> 2, cl = lane & 3;
    const int bx = blockIdx.x;
    const int wr = wid * 32;           // mma warp row base (wid<4)
    const int colg = bx * 8 + 2 * cl;

    // ldmatrix lane address components
    const int a_row = (lane & 15);
    const int a_col = (lane >> 4) << 3;
    const int b_row = (lane & 7) + ((lane >> 4) << 3);
    const int b_col = (lane & 8);

    // load W_h slice once: rows g*1024 + bx*8 + j  ->  Bs[g*8+j][0..1023]
    #pragma unroll
    for (int i = 0; i < 16; ++i) {
        int idx = tid + i * 256;            // 0..4095
        int n = idx >> 7, cc = idx & 127;
        int g = n >> 3, j = n & 7;
        cpa16(Bs + n*1032 + cc*8,
              WhT + (size_t)(g*1024 + bx*8 + j) * 1024 + cc*8);
    }
    CPA_COMMIT();
    cpa_wait<0>();
    __syncthreads();

    float cc8[8];
    #pragma unroll
    for (int i = 0; i < 8; ++i) cc8[i] = 0.f;

    auto loadA = [&](__half* dst, const __half* hsrc, int kt) {
        #pragma unroll
        for (int i = 0; i < 4; ++i) {
            int idx = tid + i * 256;        // 0..1023
            int row = idx >> 3, ccc = idx & 7;
            cpa16(dst + row*72 + ccc*8, hsrc + (size_t)row*1024 + kt*64 + ccc*8);
        }
    };

    for (int t = 0; t < TT; ++t) {
        // prefetch X gate values (independent of h) into registers
        float2 xv[2][2][4];
        if (wid < 4) {
            const float* Xt = X + (size_t)t * BB * G4;
            #pragma unroll
            for (int mt = 0; mt < 2; ++mt)
                #pragma unroll
                for (int e = 0; e < 2; ++e) {
                    int row = wr + mt*16 + r + e*8;
                    const float* xb = Xt + (size_t)row * 4096 + colg;
                    #pragma unroll
                    for (int g = 0; g < 4; ++g)
                        xv[mt][e][g] = *(const float2*)(xb + g * 1024);
                }
        }

        float acc[2][4][4];
        #pragma unroll
        for (int i = 0; i < 2; ++i)
            #pragma unroll
            for (int j = 0; j < 4; ++j)
                #pragma unroll
                for (int k = 0; k < 4; ++k) acc[i][j][k] = 0.f;

        if (t > 0) {
            // single wait: all 128 producer CTAs must have published step t-1
            if (wid == 4) {
                const int base = lane * 4;
                bool ok = false;
                do {
                    int a = ldacq(flags + base + 0);
                    int b = ldacq(flags + base + 1);
                    int c = ldacq(flags + base + 2);
                    int d = ldacq(flags + base + 3);
                    ok = (a >= t) & (b >= t) & (c >= t) & (d >= t);
                } while (!__all_sync(0xffffffffu, ok));
            }
            __syncthreads();

            const __half* hsrc = H + (size_t)(t - 1) * BB * NH;
            #pragma unroll
            for (int s = 0; s < 3; ++s) { loadA(As + s*AST, hsrc, s); CPA_COMMIT(); }

            #pragma unroll 1
            for (int kt = 0; kt < 16; ++kt) {
                cpa_wait<2>();
                __syncthreads();
                if (kt + 3 < 16) loadA(As + ((kt + 3) & 3) * AST, hsrc, kt + 3);
                CPA_COMMIT();

                if (wid < 4) {
                    const __half* sA = As + (kt & 3) * AST;
                    const __half* sBk = Bs + kt * 64;
                    #pragma unroll
                    for (int ks = 0; ks < 4; ++ks) {
                        const int k0 = ks * 16;
                        unsigned af[2][4], bf01[4], bf23[4];
                        ldsm_x4(af[0], sA + (wr      + a_row)*72 + k0 + a_col);
                        ldsm_x4(af[1], sA + (wr + 16 + a_row)*72 + k0 + a_col);
                        ldsm_x4(bf01, sBk + (size_t)(b_row     )*1032 + k0 + b_col);
                        ldsm_x4(bf23, sBk + (size_t)(b_row + 16)*1032 + k0 + b_col);
                        #pragma unroll
                        for (int mt = 0; mt < 2; ++mt) {
                            mma16(acc[mt][0], af[mt], bf01 + 0);
                            mma16(acc[mt][1], af[mt], bf01 + 2);
                            mma16(acc[mt][2], af[mt], bf23 + 0);
                            mma16(acc[mt][3], af[mt], bf23 + 2);
                        }
                    }
                }
            }
        }

        // gates + state update in registers (mma warps only)
        if (wid < 4) {
            #pragma unroll
            for (int mt = 0; mt < 2; ++mt)
                #pragma unroll
                for (int e = 0; e < 2; ++e) {
                    const int row = wr + mt*16 + r + e*8;
                    const int q = 2 * e;
                    const float lf0 = acc[mt][0][q]   + xv[mt][e][0].x;
                    const float lf1 = acc[mt][0][q+1] + xv[mt][e][0].y;
                    const float li0 = acc[mt][1][q]   + xv[mt][e][1].x;
                    const float li1 = acc[mt][1][q+1] + xv[mt][e][1].y;
                    const float lo0 = acc[mt][2][q]   + xv[mt][e][2].x;
                    const float lo1 = acc[mt][2][q+1] + xv[mt][e][2].y;
                    const float lg0 = acc[mt][3][q]   + xv[mt][e][3].x;
                    const float lg1 = acc[mt][3][q+1] + xv[mt][e][3].y;
                    const int ci = (mt*2 + e) * 2;
                    const float c0 = sigf(lf0) * cc8[ci]   + sigf(li0) * tanhf(lg0);
                    const float c1 = sigf(lf1) * cc8[ci+1] + sigf(li1) * tanhf(lg1);
                    cc8[ci] = c0; cc8[ci+1] = c1;
                    const float h0 = sigf(lo0) * tanhf(c0);
                    const float h1 = sigf(lo1) * tanhf(c1);
                    *(__half2*)&H[(size_t)t*BB*NH + (size_t)row*1024 + colg] =
                        __floats2half2_rn(h0, h1);
                }
        }

        __syncthreads();   // all H stores of this CTA ordered before the release
        if (tid == 0 && t + 1 < TT) {
            asm volatile("st.release.gpu.global.b32 [%0], %1;"
                         :: "l"(flags + bx), "r"(t + 1) : "memory");
        }
    }
}

// ---------------- launch ----------------
extern "C" void kernel_launch(void* const* d_in, const int* in_sizes, int n_in,
                              void* d_out, int out_size) {
    (void)in_sizes; (void)n_in; (void)out_size;
    const float* inputs = (const float*)d_in[0];
    const float* emb    = (const float*)d_in[1];
    const float* w0     = (const float*)d_in[2];
    const float* b0     = (const float*)d_in[3];
    const float* w1     = (const float*)d_in[4];
    const float* b1     = (const float*)d_in[5];
    const float* outw   = (const float*)d_in[6];
    const float* outb   = (const float*)d_in[7];
    float* out = (float*)d_out;

    __half *inph, *embs, *H0, *H1, *embT, *w0xT, *w0hT, *w1xT, *w1hT, *owT;
    float *X;
    int *flg;
    cudaGetSymbolAddress((void**)&inph, g_inph);
    cudaGetSymbolAddress((void**)&embs, g_embs);
    cudaGetSymbolAddress((void**)&X,    g_X);
    cudaGetSymbolAddress((void**)&H0,   g_H0);
    cudaGetSymbolAddress((void**)&H1,   g_H1);
    cudaGetSymbolAddress((void**)&embT, g_embT);
    cudaGetSymbolAddress((void**)&w0xT, g_w0xT);
    cudaGetSymbolAddress((void**)&w0hT, g_w0hT);
    cudaGetSymbolAddress((void**)&w1xT, g_w1xT);
    cudaGetSymbolAddress((void**)&w1hT, g_w1hT);
    cudaGetSymbolAddress((void**)&owT,  g_owT);
    cudaGetSymbolAddress((void**)&flg,  g_flags);

    cudaFuncSetAttribute(lstm_layer,     cudaFuncAttributeMaxDynamicSharedMemorySize, LSTM_SMEM);
    cudaFuncSetAttribute(gemm16<float>,  cudaFuncAttributeMaxDynamicSharedMemorySize, GEMM_SMEM);
    cudaFuncSetAttribute(gemm16<__half>, cudaFuncAttributeMaxDynamicSharedMemorySize, GEMM_SMEM);

    // prep
    f2h_kernel<<<1024, 256>>>(inputs, inph, TB * VV);
    {
        dim3 blk(32, 8);
        transpose_cvt<<<dim3(VV/32, EE/32), blk>>>(emb,                EE, embT, VV, EE);
        transpose_cvt<<<dim3(EE/32, G4/32), blk>>>(w0,                 G4, w0xT, EE, G4);
        transpose_cvt<<<dim3(NH/32, G4/32), blk>>>(w0 + (size_t)EE*G4, G4, w0hT, NH, G4);
        transpose_cvt<<<dim3(NH/32, G4/32), blk>>>(w1,                 G4, w1xT, NH, G4);
        transpose_cvt<<<dim3(NH/32, G4/32), blk>>>(w1 + (size_t)NH*G4, G4, w1hT, NH, G4);
        transpose_cvt<<<dim3(NH/32, VV/32), blk>>>(outw,               VV, owT,  NH, VV);
    }
    zero_flags<<<1, 128>>>();

    // embs = inputs @ emb
    gemm16<__half><<<dim3(EE/128, TB/128), 256, GEMM_SMEM>>>(inph, VV, embT, embs, EE, nullptr, TB, EE, VV);
    // X = embs @ W0x + b0
    gemm16<float><<<dim3(G4/128, TB/128), 256, GEMM_SMEM>>>(embs, EE, w0xT, X, G4, b0, TB, G4, EE);
    // layer 0 (persistent)
    lstm_layer<<<128, 256, LSTM_SMEM>>>(w0hT, X, H0, flg);
    // X = H0 @ W1x + b1
    gemm16<float><<<dim3(G4/128, TB/128), 256, GEMM_SMEM>>>(H0, NH, w1xT, X, G4, b1, TB, G4, NH);
    // layer 1 (persistent)
    lstm_layer<<<128, 256, LSTM_SMEM>>>(w1hT, X, H1, flg + 128);
    // logits = H1 @ out_w + out_b
    gemm16<float><<<dim3(VV/128, TB/128), 256, GEMM_SMEM>>>(H1, NH, owT, out, VV, outb, TB, VV, NH);
}

// round 6
// speedup vs baseline: 1.2688x; 1.1143x over previous
#include <cuda_runtime.h>
#include <cuda_fp16.h>
#include <stdint.h>

#define TT 256
#define BB 128
#define VV 256
#define EE 512
#define NH 1024
#define TB (TT*BB)          // 32768
#define G4 (4*NH)           // 4096

// ---------------- static device scratch ----------------
__device__ __align__(16) __half g_inph[(size_t)TB*VV];
__device__ __align__(16) __half g_embs[(size_t)TB*EE];
__device__ __align__(16) float  g_X[(size_t)TB*G4];
__device__ __align__(16) __half g_H0[(size_t)TB*NH];
__device__ __align__(16) __half g_H1[(size_t)TB*NH];
__device__ __align__(16) __half g_embT[EE*VV];           // [512][256]
__device__ __align__(16) __half g_w0xT[(size_t)G4*EE];   // [4096][512]
__device__ __align__(16) __half g_w0hT[(size_t)G4*NH];   // [4096][1024]
__device__ __align__(16) __half g_w1xT[(size_t)G4*NH];   // [4096][1024]
__device__ __align__(16) __half g_w1hT[(size_t)G4*NH];   // [4096][1024]
__device__ __align__(16) __half g_owT[VV*NH];            // [256][1024]
__device__ int g_flags[2][128];

// ---------------- helpers ----------------
__device__ __forceinline__ void mma16(float d[4], const unsigned a[4], const unsigned b[2]) {
    asm volatile(
        "mma.sync.aligned.m16n8k16.row.col.f32.f16.f16.f32 "
        "{%0,%1,%2,%3}, {%4,%5,%6,%7}, {%8,%9}, {%0,%1,%2,%3};\n"
        : "+f"(d[0]), "+f"(d[1]), "+f"(d[2]), "+f"(d[3])
        : "r"(a[0]), "r"(a[1]), "r"(a[2]), "r"(a[3]), "r"(b[0]), "r"(b[1]));
}
__device__ __forceinline__ void ldsm_x4(unsigned r[4], const __half* p) {
    unsigned a = (unsigned)__cvta_generic_to_shared(p);
    asm volatile("ldmatrix.sync.aligned.m8n8.x4.shared.b16 {%0,%1,%2,%3}, [%4];\n"
        : "=r"(r[0]), "=r"(r[1]), "=r"(r[2]), "=r"(r[3]) : "r"(a));
}
__device__ __forceinline__ void cpa16(__half* dst, const __half* src) {
    unsigned d = (unsigned)__cvta_generic_to_shared(dst);
    asm volatile("cp.async.cg.shared.global [%0], [%1], 16;\n" :: "r"(d), "l"(src));
}
#define CPA_COMMIT() asm volatile("cp.async.commit_group;\n" ::: "memory")
template <int N> __device__ __forceinline__ void cpa_wait() {
    asm volatile("cp.async.wait_group %0;\n" :: "n"(N) : "memory");
}
__device__ __forceinline__ int ldacq(const int* p) {
    int v;
    asm volatile("ld.acquire.gpu.global.b32 %0, [%1];" : "=r"(v) : "l"(p) : "memory");
    return v;
}
__device__ __forceinline__ void cstore2(float* C, size_t i, float a, float b) {
    *(float2*)&C[i] = make_float2(a, b);
}
__device__ __forceinline__ void cstore2(__half* C, size_t i, float a, float b) {
    *(__half2*)&C[i] = __floats2half2_rn(a, b);
}
__device__ __forceinline__ float sigf(float x) { return 1.f / (1.f + __expf(-x)); }

__global__ void zero_flags() {
    if (threadIdx.x < 128) {
        g_flags[0][threadIdx.x] = 0;
        g_flags[1][threadIdx.x] = 0;
    }
}
__global__ void f2h_kernel(const float* __restrict__ s, __half* __restrict__ d, int n) {
    for (int i = blockIdx.x * blockDim.x + threadIdx.x; i < n; i += gridDim.x * blockDim.x)
        d[i] = __float2half(s[i]);
}
// src fp32 [K][N] (row stride lds) -> dst fp16 [N][K]
__global__ void transpose_cvt(const float* __restrict__ src, int lds,
                              __half* __restrict__ dst, int K, int N) {
    __shared__ float tile[32][33];
    int kb = blockIdx.x * 32, nb = blockIdx.y * 32;
    #pragma unroll
    for (int i = threadIdx.y; i < 32; i += 8) {
        int k = kb + i, n = nb + threadIdx.x;
        tile[i][threadIdx.x] = (k < K && n < N) ? src[(size_t)k * lds + n] : 0.f;
    }
    __syncthreads();
    #pragma unroll
    for (int i = threadIdx.y; i < 32; i += 8) {
        int n = nb + i, k = kb + threadIdx.x;
        if (n < N && k < K) dst[(size_t)n * K + k] = __float2half(tile[threadIdx.x][i]);
    }
}

// ---------------- fp16 GEMM: C[M,N] = A[M,K] @ Bt[N,K]^T (+bias) ----------------
// CTA tile 128x128, K-tile 32, 4-stage cp.async, 256 thr (8 warps, 2x4), warp 64x32.
#define GAST (128*40)
#define GBST (128*40)
#define GEMM_SMEM ((4*(GAST+GBST))*2)

template <typename TOUT>
__global__ void __launch_bounds__(256, 2) gemm16(
    const __half* __restrict__ A, int lda,
    const __half* __restrict__ Bt,
    TOUT* __restrict__ C, int ldc,
    const float* __restrict__ bias,
    int M, int N, int K)
{
    extern __shared__ __half sm[];
    __half* As = sm;
    __half* Bs = sm + 4*GAST;

    const int tid = threadIdx.x;
    const int bm = blockIdx.y * 128, bn = blockIdx.x * 128;
    const int wid = tid >> 5, lane = tid & 31;
    const int wr = (wid & 1) * 64, wc = (wid >> 1) * 32;
    const int r = lane >> 2, cl = lane & 3;

    float acc[4][4][4];
    #pragma unroll
    for (int i = 0; i < 4; ++i)
        #pragma unroll
        for (int j = 0; j < 4; ++j)
            #pragma unroll
            for (int k = 0; k < 4; ++k) acc[i][j][k] = 0.f;

    auto loadG = [&](int s, int kt) {
        #pragma unroll
        for (int i = 0; i < 2; ++i) {
            int idx = tid + i * 256;
            int row = idx >> 2, cc = idx & 3;
            cpa16(As + s*GAST + row*40 + cc*8,
                  A + (size_t)(bm + row) * lda + kt*32 + cc*8);
            cpa16(Bs + s*GBST + row*40 + cc*8,
                  Bt + (size_t)(bn + row) * K + kt*32 + cc*8);
        }
    };

    const int ktiles = K >> 5;
    #pragma unroll
    for (int s = 0; s < 3; ++s) { if (s < ktiles) loadG(s, s); CPA_COMMIT(); }

    // ldmatrix lane address components
    const int a_row = (lane & 15);
    const int a_col = (lane >> 4) << 3;
    const int b_row = (lane & 7) + ((lane >> 4) << 3);
    const int b_col = (lane & 8);

    for (int kt = 0; kt < ktiles; ++kt) {
        cpa_wait<2>();
        __syncthreads();
        if (kt + 3 < ktiles) loadG((kt + 3) & 3, kt + 3);
        CPA_COMMIT();

        const __half* sA = As + (kt & 3) * GAST;
        const __half* sB = Bs + (kt & 3) * GBST;
        #pragma unroll
        for (int ks = 0; ks < 2; ++ks) {
            const int k0 = ks * 16;
            unsigned af[4][4], bf01[4], bf23[4];
            #pragma unroll
            for (int mt = 0; mt < 4; ++mt)
                ldsm_x4(af[mt], sA + (wr + mt*16 + a_row)*40 + k0 + a_col);
            ldsm_x4(bf01, sB + (wc      + b_row)*40 + k0 + b_col);
            ldsm_x4(bf23, sB + (wc + 16 + b_row)*40 + k0 + b_col);
            #pragma unroll
            for (int mt = 0; mt < 4; ++mt) {
                mma16(acc[mt][0], af[mt], bf01 + 0);
                mma16(acc[mt][1], af[mt], bf01 + 2);
                mma16(acc[mt][2], af[mt], bf23 + 0);
                mma16(acc[mt][3], af[mt], bf23 + 2);
            }
        }
    }

    #pragma unroll
    for (int mt = 0; mt < 4; ++mt)
        #pragma unroll
        for (int nt = 0; nt < 4; ++nt) {
            const int row = bm + wr + mt*16 + r;
            const int col = bn + wc + nt*8 + 2*cl;
            const float b0 = bias ? bias[col]     : 0.f;
            const float b1 = bias ? bias[col + 1] : 0.f;
            cstore2(C, (size_t)row * ldc + col,       acc[mt][nt][0] + b0, acc[mt][nt][1] + b1);
            cstore2(C, (size_t)(row + 8) * ldc + col, acc[mt][nt][2] + b0, acc[mt][nt][3] + b1);
        }
}

// ---------------- persistent LSTM layer kernel (R3 compute structure) ----------------
// 128 CTAs (1/SM). CTA bx owns hidden cols [bx*8, bx*8+8) of all 4 gates
// (GEMM N=32 = 4 gates x 8 cols, K=1024). W_h slice (64KB) resident in smem.
// 8 warps, each mma over 16 rows x 32 cols; direct LDS fragment loads.
// Sync: warp-0 flag poll (4 flags/lane + __all_sync); producers st.release.
#define AST (128*72)
#define LSTM_SMEM ((32*1032 + 4*AST)*2)

__global__ void __launch_bounds__(256, 1) lstm_layer(
    const __half* __restrict__ WhT,    // [4096][1024]
    const float*  __restrict__ X,      // [T*128][4096]
    __half* __restrict__ H,            // [T*128][1024]
    int* __restrict__ flags)           // [128]
{
    extern __shared__ __half sm[];
    __half* Bs = sm;                   // 32 x 1032 (n = gate*8+j, k = 0..1023)
    __half* As = sm + 32*1032;         // 4 stages x 128 x 72

    const int tid = threadIdx.x, lane = tid & 31, wid = tid >> 5;
    const int r = lane >> 2, cl = lane & 3;
    const int bx = blockIdx.x;
    const int wr = wid * 16;
    const int row0 = wr + r, row1 = row0 + 8;
    const int jj = 2 * cl;
    const int colg = bx * 8 + jj;

    // load W_h slice once: rows g*1024 + bx*8 + j  ->  Bs[g*8+j][0..1023]
    #pragma unroll
    for (int i = 0; i < 16; ++i) {
        int idx = tid + i * 256;            // 0..4095
        int n = idx >> 7, cc = idx & 127;
        int g = n >> 3, j = n & 7;
        cpa16(Bs + n*1032 + cc*8,
              WhT + (size_t)(g*1024 + bx*8 + j) * 1024 + cc*8);
    }
    CPA_COMMIT();
    cpa_wait<0>();
    __syncthreads();

    float c0 = 0.f, c1 = 0.f, c2 = 0.f, c3 = 0.f;

    auto loadA = [&](__half* dst, const __half* hsrc, int kt) {
        #pragma unroll
        for (int i = 0; i < 4; ++i) {
            int idx = tid + i * 256;        // 0..1023
            int row = idx >> 3, cc = idx & 7;
            cpa16(dst + row*72 + cc*8, hsrc + (size_t)row*1024 + kt*64 + cc*8);
        }
    };

    for (int t = 0; t < TT; ++t) {
        float acc[4][4];
        #pragma unroll
        for (int i = 0; i < 4; ++i)
            #pragma unroll
            for (int j = 0; j < 4; ++j) acc[i][j] = 0.f;

        if (t > 0) {
            // single wait: all 128 producer CTAs must have published step t-1
            if (wid == 0) {
                const int base = lane * 4;
                bool ok = false;
                do {
                    int a = ldacq(flags + base + 0);
                    int b = ldacq(flags + base + 1);
                    int c = ldacq(flags + base + 2);
                    int d = ldacq(flags + base + 3);
                    ok = (a >= t) & (b >= t) & (c >= t) & (d >= t);
                } while (!__all_sync(0xffffffffu, ok));
            }
            __syncthreads();

            const __half* hsrc = H + (size_t)(t - 1) * BB * NH;
            #pragma unroll
            for (int s = 0; s < 3; ++s) { loadA(As + s*AST, hsrc, s); CPA_COMMIT(); }

            #pragma unroll 1
            for (int kt = 0; kt < 16; ++kt) {
                cpa_wait<2>();
                __syncthreads();
                if (kt + 3 < 16) loadA(As + ((kt + 3) & 3) * AST, hsrc, kt + 3);
                CPA_COMMIT();

                const __half* sA = As + (kt & 3) * AST;
                #pragma unroll
                for (int ks = 0; ks < 4; ++ks) {
                    const int k0 = ks * 16;
                    unsigned af[4];
                    af[0] = *(const unsigned*)&sA[row0*72 + k0 + jj];
                    af[1] = *(const unsigned*)&sA[row1*72 + k0 + jj];
                    af[2] = *(const unsigned*)&sA[row0*72 + k0 + jj + 8];
                    af[3] = *(const unsigned*)&sA[row1*72 + k0 + jj + 8];
                    #pragma unroll
                    for (int nt = 0; nt < 4; ++nt) {
                        const __half* bp = Bs + (size_t)(nt*8 + r)*1032 + kt*64 + k0 + jj;
                        unsigned bf[2];
                        bf[0] = *(const unsigned*)bp;
                        bf[1] = *(const unsigned*)(bp + 8);
                        mma16(acc[nt], af, bf);
                    }
                }
            }
        }

        // gates + state update, all in registers (X loaded here, not held live)
        const float* Xt = X + (size_t)t * (BB * G4);
        {
            const float* xb = Xt + (size_t)row0 * 4096 + colg;
            float2 xf = *(const float2*)(xb);
            float2 xi = *(const float2*)(xb + 1024);
            float2 xo = *(const float2*)(xb + 2048);
            float2 xg = *(const float2*)(xb + 3072);
            float f  = sigf(acc[0][0] + xf.x), ig  = sigf(acc[1][0] + xi.x);
            float o  = sigf(acc[2][0] + xo.x), gg  = tanhf(acc[3][0] + xg.x);
            c0 = f * c0 + ig * gg;
            float f1 = sigf(acc[0][1] + xf.y), ig1 = sigf(acc[1][1] + xi.y);
            float o1 = sigf(acc[2][1] + xo.y), gg1 = tanhf(acc[3][1] + xg.y);
            c1 = f1 * c1 + ig1 * gg1;
            __half2 hv = __floats2half2_rn(o * tanhf(c0), o1 * tanhf(c1));
            *(__half2*)&H[(size_t)t*BB*NH + (size_t)row0*1024 + colg] = hv;
        }
        {
            const float* xb = Xt + (size_t)row1 * 4096 + colg;
            float2 xf = *(const float2*)(xb);
            float2 xi = *(const float2*)(xb + 1024);
            float2 xo = *(const float2*)(xb + 2048);
            float2 xg = *(const float2*)(xb + 3072);
            float f  = sigf(acc[0][2] + xf.x), ig  = sigf(acc[1][2] + xi.x);
            float o  = sigf(acc[2][2] + xo.x), gg  = tanhf(acc[3][2] + xg.x);
            c2 = f * c2 + ig * gg;
            float f1 = sigf(acc[0][3] + xf.y), ig1 = sigf(acc[1][3] + xi.y);
            float o1 = sigf(acc[2][3] + xo.y), gg1 = tanhf(acc[3][3] + xg.y);
            c3 = f1 * c3 + ig1 * gg1;
            __half2 hv = __floats2half2_rn(o * tanhf(c2), o1 * tanhf(c3));
            *(__half2*)&H[(size_t)t*BB*NH + (size_t)row1*1024 + colg] = hv;
        }

        __syncthreads();   // all H stores of this CTA ordered before the release
        if (tid == 0 && t + 1 < TT) {
            asm volatile("st.release.gpu.global.b32 [%0], %1;"
                         :: "l"(flags + bx), "r"(t + 1) : "memory");
        }
    }
}

// ---------------- launch ----------------
extern "C" void kernel_launch(void* const* d_in, const int* in_sizes, int n_in,
                              void* d_out, int out_size) {
    (void)in_sizes; (void)n_in; (void)out_size;
    const float* inputs = (const float*)d_in[0];
    const float* emb    = (const float*)d_in[1];
    const float* w0     = (const float*)d_in[2];
    const float* b0     = (const float*)d_in[3];
    const float* w1     = (const float*)d_in[4];
    const float* b1     = (const float*)d_in[5];
    const float* outw   = (const float*)d_in[6];
    const float* outb   = (const float*)d_in[7];
    float* out = (float*)d_out;

    __half *inph, *embs, *H0, *H1, *embT, *w0xT, *w0hT, *w1xT, *w1hT, *owT;
    float *X;
    int *flg;
    cudaGetSymbolAddress((void**)&inph, g_inph);
    cudaGetSymbolAddress((void**)&embs, g_embs);
    cudaGetSymbolAddress((void**)&X,    g_X);
    cudaGetSymbolAddress((void**)&H0,   g_H0);
    cudaGetSymbolAddress((void**)&H1,   g_H1);
    cudaGetSymbolAddress((void**)&embT, g_embT);
    cudaGetSymbolAddress((void**)&w0xT, g_w0xT);
    cudaGetSymbolAddress((void**)&w0hT, g_w0hT);
    cudaGetSymbolAddress((void**)&w1xT, g_w1xT);
    cudaGetSymbolAddress((void**)&w1hT, g_w1hT);
    cudaGetSymbolAddress((void**)&owT,  g_owT);
    cudaGetSymbolAddress((void**)&flg,  g_flags);

    cudaFuncSetAttribute(lstm_layer,     cudaFuncAttributeMaxDynamicSharedMemorySize, LSTM_SMEM);
    cudaFuncSetAttribute(gemm16<float>,  cudaFuncAttributeMaxDynamicSharedMemorySize, GEMM_SMEM);
    cudaFuncSetAttribute(gemm16<__half>, cudaFuncAttributeMaxDynamicSharedMemorySize, GEMM_SMEM);

    // prep
    f2h_kernel<<<1024, 256>>>(inputs, inph, TB * VV);
    {
        dim3 blk(32, 8);
        transpose_cvt<<<dim3(VV/32, EE/32), blk>>>(emb,                EE, embT, VV, EE);
        transpose_cvt<<<dim3(EE/32, G4/32), blk>>>(w0,                 G4, w0xT, EE, G4);
        transpose_cvt<<<dim3(NH/32, G4/32), blk>>>(w0 + (size_t)EE*G4, G4, w0hT, NH, G4);
        transpose_cvt<<<dim3(NH/32, G4/32), blk>>>(w1,                 G4, w1xT, NH, G4);
        transpose_cvt<<<dim3(NH/32, G4/32), blk>>>(w1 + (size_t)NH*G4, G4, w1hT, NH, G4);
        transpose_cvt<<<dim3(NH/32, VV/32), blk>>>(outw,               VV, owT,  NH, VV);
    }
    zero_flags<<<1, 128>>>();

    // embs = inputs @ emb
    gemm16<__half><<<dim3(EE/128, TB/128), 256, GEMM_SMEM>>>(inph, VV, embT, embs, EE, nullptr, TB, EE, VV);
    // X = embs @ W0x + b0
    gemm16<float><<<dim3(G4/128, TB/128), 256, GEMM_SMEM>>>(embs, EE, w0xT, X, G4, b0, TB, G4, EE);
    // layer 0 (persistent)
    lstm_layer<<<128, 256, LSTM_SMEM>>>(w0hT, X, H0, flg);
    // X = H0 @ W1x + b1
    gemm16<float><<<dim3(G4/128, TB/128), 256, GEMM_SMEM>>>(H0, NH, w1xT, X, G4, b1, TB, G4, NH);
    // layer 1 (persistent)
    lstm_layer<<<128, 256, LSTM_SMEM>>>(w1hT, X, H1, flg + 128);
    // logits = H1 @ out_w + out_b
    gemm16<float><<<dim3(VV/128, TB/128), 256, GEMM_SMEM>>>(H1, NH, owT, out, VV, outb, TB, VV, NH);
}

// round 7
// speedup vs baseline: 1.6688x; 1.3153x over previous
#include <cuda_runtime.h>
#include <cuda_fp16.h>
#include <stdint.h>

#define TT 256
#define BB 128
#define VV 256
#define EE 512
#define NH 1024
#define TB (TT*BB)          // 32768
#define G4 (4*NH)           // 4096

// ---------------- static device scratch ----------------
__device__ __align__(16) __half g_inph[(size_t)TB*VV];
__device__ __align__(16) __half g_embs[(size_t)TB*EE];
__device__ __align__(16) float  g_X[(size_t)TB*G4];
__device__ __align__(16) __half g_H0[(size_t)TB*NH];
__device__ __align__(16) __half g_H1[(size_t)TB*NH];
__device__ __align__(16) __half g_embT[EE*VV];           // [512][256]
__device__ __align__(16) __half g_w0xT[(size_t)G4*EE];   // [4096][512]
__device__ __align__(16) __half g_w0hT[(size_t)G4*NH];   // [4096][1024]
__device__ __align__(16) __half g_w1xT[(size_t)G4*NH];   // [4096][1024]
__device__ __align__(16) __half g_w1hT[(size_t)G4*NH];   // [4096][1024]
__device__ __align__(16) __half g_owT[VV*NH];            // [256][1024]
__device__ int g_ctr[2];

// ---------------- helpers ----------------
__device__ __forceinline__ void mma16(float d[4], const unsigned a[4], const unsigned b[2]) {
    asm volatile(
        "mma.sync.aligned.m16n8k16.row.col.f32.f16.f16.f32 "
        "{%0,%1,%2,%3}, {%4,%5,%6,%7}, {%8,%9}, {%0,%1,%2,%3};\n"
        : "+f"(d[0]), "+f"(d[1]), "+f"(d[2]), "+f"(d[3])
        : "r"(a[0]), "r"(a[1]), "r"(a[2]), "r"(a[3]), "r"(b[0]), "r"(b[1]));
}
__device__ __forceinline__ void ldsm_x4(unsigned r[4], const __half* p) {
    unsigned a = (unsigned)__cvta_generic_to_shared(p);
    asm volatile("ldmatrix.sync.aligned.m8n8.x4.shared.b16 {%0,%1,%2,%3}, [%4];\n"
        : "=r"(r[0]), "=r"(r[1]), "=r"(r[2]), "=r"(r[3]) : "r"(a));
}
__device__ __forceinline__ void cpa16(__half* dst, const __half* src) {
    unsigned d = (unsigned)__cvta_generic_to_shared(dst);
    asm volatile("cp.async.cg.shared.global [%0], [%1], 16;\n" :: "r"(d), "l"(src));
}
#define CPA_COMMIT() asm volatile("cp.async.commit_group;\n" ::: "memory")
template <int N> __device__ __forceinline__ void cpa_wait() {
    asm volatile("cp.async.wait_group %0;\n" :: "n"(N) : "memory");
}
__device__ __forceinline__ void cstore2(float* C, size_t i, float a, float b) {
    *(float2*)&C[i] = make_float2(a, b);
}
__device__ __forceinline__ void cstore2(__half* C, size_t i, float a, float b) {
    *(__half2*)&C[i] = __floats2half2_rn(a, b);
}
__device__ __forceinline__ float sigf(float x) { return 1.f / (1.f + __expf(-x)); }

__global__ void zero_i(int* p) { if (threadIdx.x < 2) p[threadIdx.x] = 0; }
__global__ void f2h_kernel(const float* __restrict__ s, __half* __restrict__ d, int n) {
    for (int i = blockIdx.x * blockDim.x + threadIdx.x; i < n; i += gridDim.x * blockDim.x)
        d[i] = __float2half(s[i]);
}
// src fp32 [K][N] (row stride lds) -> dst fp16 [N][K]
__global__ void transpose_cvt(const float* __restrict__ src, int lds,
                              __half* __restrict__ dst, int K, int N) {
    __shared__ float tile[32][33];
    int kb = blockIdx.x * 32, nb = blockIdx.y * 32;
    #pragma unroll
    for (int i = threadIdx.y; i < 32; i += 8) {
        int k = kb + i, n = nb + threadIdx.x;
        tile[i][threadIdx.x] = (k < K && n < N) ? src[(size_t)k * lds + n] : 0.f;
    }
    __syncthreads();
    #pragma unroll
    for (int i = threadIdx.y; i < 32; i += 8) {
        int n = nb + i, k = kb + threadIdx.x;
        if (n < N && k < K) dst[(size_t)n * K + k] = __float2half(tile[threadIdx.x][i]);
    }
}

// ---------------- fp16 GEMM: C[M,N] = A[M,K] @ Bt[N,K]^T (+bias) ----------------
// CTA tile 128x128, K-tile 32, 4-stage cp.async, 256 thr (8 warps, 2x4), warp 64x32.
#define GAST (128*40)
#define GBST (128*40)
#define GEMM_SMEM ((4*(GAST+GBST))*2)

template <typename TOUT>
__global__ void __launch_bounds__(256, 2) gemm16(
    const __half* __restrict__ A, int lda,
    const __half* __restrict__ Bt,
    TOUT* __restrict__ C, int ldc,
    const float* __restrict__ bias,
    int M, int N, int K)
{
    extern __shared__ __half sm[];
    __half* As = sm;
    __half* Bs = sm + 4*GAST;

    const int tid = threadIdx.x;
    const int bm = blockIdx.y * 128, bn = blockIdx.x * 128;
    const int wid = tid >> 5, lane = tid & 31;
    const int wr = (wid & 1) * 64, wc = (wid >> 1) * 32;
    const int r = lane >> 2, cl = lane & 3;

    float acc[4][4][4];
    #pragma unroll
    for (int i = 0; i < 4; ++i)
        #pragma unroll
        for (int j = 0; j < 4; ++j)
            #pragma unroll
            for (int k = 0; k < 4; ++k) acc[i][j][k] = 0.f;

    auto loadG = [&](int s, int kt) {
        #pragma unroll
        for (int i = 0; i < 2; ++i) {
            int idx = tid + i * 256;
            int row = idx >> 2, cc = idx & 3;
            cpa16(As + s*GAST + row*40 + cc*8,
                  A + (size_t)(bm + row) * lda + kt*32 + cc*8);
            cpa16(Bs + s*GBST + row*40 + cc*8,
                  Bt + (size_t)(bn + row) * K + kt*32 + cc*8);
        }
    };

    const int ktiles = K >> 5;
    #pragma unroll
    for (int s = 0; s < 3; ++s) { if (s < ktiles) loadG(s, s); CPA_COMMIT(); }

    // ldmatrix lane address components
    const int a_row = (lane & 15);
    const int a_col = (lane >> 4) << 3;
    const int b_row = (lane & 7) + ((lane >> 4) << 3);
    const int b_col = (lane & 8);

    for (int kt = 0; kt < ktiles; ++kt) {
        cpa_wait<2>();
        __syncthreads();
        if (kt + 3 < ktiles) loadG((kt + 3) & 3, kt + 3);
        CPA_COMMIT();

        const __half* sA = As + (kt & 3) * GAST;
        const __half* sB = Bs + (kt & 3) * GBST;
        #pragma unroll
        for (int ks = 0; ks < 2; ++ks) {
            const int k0 = ks * 16;
            unsigned af[4][4], bf01[4], bf23[4];
            #pragma unroll
            for (int mt = 0; mt < 4; ++mt)
                ldsm_x4(af[mt], sA + (wr + mt*16 + a_row)*40 + k0 + a_col);
            ldsm_x4(bf01, sB + (wc      + b_row)*40 + k0 + b_col);
            ldsm_x4(bf23, sB + (wc + 16 + b_row)*40 + k0 + b_col);
            #pragma unroll
            for (int mt = 0; mt < 4; ++mt) {
                mma16(acc[mt][0], af[mt], bf01 + 0);
                mma16(acc[mt][1], af[mt], bf01 + 2);
                mma16(acc[mt][2], af[mt], bf23 + 0);
                mma16(acc[mt][3], af[mt], bf23 + 2);
            }
        }
    }

    #pragma unroll
    for (int mt = 0; mt < 4; ++mt)
        #pragma unroll
        for (int nt = 0; nt < 4; ++nt) {
            const int row = bm + wr + mt*16 + r;
            const int col = bn + wc + nt*8 + 2*cl;
            const float b0 = bias ? bias[col]     : 0.f;
            const float b1 = bias ? bias[col + 1] : 0.f;
            cstore2(C, (size_t)row * ldc + col,       acc[mt][nt][0] + b0, acc[mt][nt][1] + b1);
            cstore2(C, (size_t)(row + 8) * ldc + col, acc[mt][nt][2] + b0, acc[mt][nt][3] + b1);
        }
}

// ---------------- persistent LSTM layer kernel (R3 verbatim) ----------------
// 128 CTAs (1/SM). CTA bx owns hidden cols [bx*8, bx*8+8) of all 4 gates
// (GEMM N=32 = 4 gates x 8 cols, K=1024). W_h slice (64KB) resident in smem.
// 8 warps, each mma over 16 rows x 32 cols; direct LDS fragment loads.
// Sync: single global atomic counter + one-address spin (measured best).
#define AST (128*72)
#define LSTM_SMEM ((32*1032 + 4*AST)*2)

__global__ void __launch_bounds__(256, 1) lstm_layer(
    const __half* __restrict__ WhT,    // [4096][1024]
    const float*  __restrict__ X,      // [T*128][4096]
    __half* __restrict__ H,            // [T*128][1024]
    int* __restrict__ ctr)
{
    extern __shared__ __half sm[];
    __half* Bs = sm;                   // 32 x 1032 (n = gate*8+j, k = 0..1023)
    __half* As = sm + 32*1032;         // 4 stages x 128 x 72

    const int tid = threadIdx.x, lane = tid & 31, wid = tid >> 5;
    const int r = lane >> 2, cl = lane & 3;
    const int bx = blockIdx.x;
    const int wr = wid * 16;
    const int row0 = wr + r, row1 = row0 + 8;
    const int jj = 2 * cl;
    const int colg = bx * 8 + jj;

    // load W_h slice once: rows g*1024 + bx*8 + j  ->  Bs[g*8+j][0..1023]
    #pragma unroll
    for (int i = 0; i < 16; ++i) {
        int idx = tid + i * 256;            // 0..4095
        int n = idx >> 7, cc = idx & 127;
        int g = n >> 3, j = n & 7;
        cpa16(Bs + n*1032 + cc*8,
              WhT + (size_t)(g*1024 + bx*8 + j) * 1024 + cc*8);
    }
    CPA_COMMIT();
    cpa_wait<0>();
    __syncthreads();

    float c0 = 0.f, c1 = 0.f, c2 = 0.f, c3 = 0.f;

    auto loadA = [&](__half* dst, const __half* hsrc, int kt) {
        #pragma unroll
        for (int i = 0; i < 4; ++i) {
            int idx = tid + i * 256;        // 0..1023
            int row = idx >> 3, cc = idx & 7;
            cpa16(dst + row*72 + cc*8, hsrc + (size_t)row*1024 + kt*64 + cc*8);
        }
    };

    for (int t = 0; t < TT; ++t) {
        float acc[4][4];
        #pragma unroll
        for (int i = 0; i < 4; ++i)
            #pragma unroll
            for (int j = 0; j < 4; ++j) acc[i][j] = 0.f;

        if (t > 0) {
            const __half* hsrc = H + (size_t)(t - 1) * BB * NH;
            #pragma unroll
            for (int s = 0; s < 3; ++s) { loadA(As + s*AST, hsrc, s); CPA_COMMIT(); }

            #pragma unroll 1
            for (int kt = 0; kt < 16; ++kt) {
                cpa_wait<2>();
                __syncthreads();
                if (kt + 3 < 16) loadA(As + ((kt + 3) & 3) * AST, hsrc, kt + 3);
                CPA_COMMIT();

                const __half* sA = As + (kt & 3) * AST;
                #pragma unroll
                for (int ks = 0; ks < 4; ++ks) {
                    const int k0 = ks * 16;
                    unsigned af[4];
                    af[0] = *(const unsigned*)&sA[row0*72 + k0 + jj];
                    af[1] = *(const unsigned*)&sA[row1*72 + k0 + jj];
                    af[2] = *(const unsigned*)&sA[row0*72 + k0 + jj + 8];
                    af[3] = *(const unsigned*)&sA[row1*72 + k0 + jj + 8];
                    #pragma unroll
                    for (int nt = 0; nt < 4; ++nt) {
                        const __half* bp = Bs + (size_t)(nt*8 + r)*1032 + kt*64 + k0 + jj;
                        unsigned bf[2];
                        bf[0] = *(const unsigned*)bp;
                        bf[1] = *(const unsigned*)(bp + 8);
                        mma16(acc[nt], af, bf);
                    }
                }
            }
        }

        // gates + state update, all in registers
        const float* Xt = X + (size_t)t * (BB * G4);
        {
            const float* xb = Xt + (size_t)row0 * 4096 + colg;
            float2 xf = *(const float2*)(xb);
            float2 xi = *(const float2*)(xb + 1024);
            float2 xo = *(const float2*)(xb + 2048);
            float2 xg = *(const float2*)(xb + 3072);
            float f  = sigf(acc[0][0] + xf.x), ig  = sigf(acc[1][0] + xi.x);
            float o  = sigf(acc[2][0] + xo.x), gg  = tanhf(acc[3][0] + xg.x);
            c0 = f * c0 + ig * gg;
            float f1 = sigf(acc[0][1] + xf.y), ig1 = sigf(acc[1][1] + xi.y);
            float o1 = sigf(acc[2][1] + xo.y), gg1 = tanhf(acc[3][1] + xg.y);
            c1 = f1 * c1 + ig1 * gg1;
            __half2 hv = __floats2half2_rn(o * tanhf(c0), o1 * tanhf(c1));
            *(__half2*)&H[(size_t)t*BB*NH + (size_t)row0*1024 + colg] = hv;
        }
        {
            const float* xb = Xt + (size_t)row1 * 4096 + colg;
            float2 xf = *(const float2*)(xb);
            float2 xi = *(const float2*)(xb + 1024);
            float2 xo = *(const float2*)(xb + 2048);
            float2 xg = *(const float2*)(xb + 3072);
            float f  = sigf(acc[0][2] + xf.x), ig  = sigf(acc[1][2] + xi.x);
            float o  = sigf(acc[2][2] + xo.x), gg  = tanhf(acc[3][2] + xg.x);
            c2 = f * c2 + ig * gg;
            float f1 = sigf(acc[0][3] + xf.y), ig1 = sigf(acc[1][3] + xi.y);
            float o1 = sigf(acc[2][3] + xo.y), gg1 = tanhf(acc[3][3] + xg.y);
            c3 = f1 * c3 + ig1 * gg1;
            __half2 hv = __floats2half2_rn(o * tanhf(c2), o1 * tanhf(c3));
            *(__half2*)&H[(size_t)t*BB*NH + (size_t)row1*1024 + colg] = hv;
        }

        if (t + 1 < TT) {
            __threadfence();       // release h stores GPU-wide
            __syncthreads();       // all threads' stores fenced before arrive
            if (tid == 0) {
                atomicAdd(ctr, 1);
                const int target = 128 * (t + 1);
                int v;
                do {
                    asm volatile("ld.acquire.gpu.b32 %0, [%1];" : "=r"(v) : "l"(ctr));
                } while (v < target);
            }
            __syncthreads();       // broadcast acquire to whole CTA
        }
    }
}

// ---------------- launch ----------------
extern "C" void kernel_launch(void* const* d_in, const int* in_sizes, int n_in,
                              void* d_out, int out_size) {
    (void)in_sizes; (void)n_in; (void)out_size;
    const float* inputs = (const float*)d_in[0];
    const float* emb    = (const float*)d_in[1];
    const float* w0     = (const float*)d_in[2];
    const float* b0     = (const float*)d_in[3];
    const float* w1     = (const float*)d_in[4];
    const float* b1     = (const float*)d_in[5];
    const float* outw   = (const float*)d_in[6];
    const float* outb   = (const float*)d_in[7];
    float* out = (float*)d_out;

    __half *inph, *embs, *H0, *H1, *embT, *w0xT, *w0hT, *w1xT, *w1hT, *owT;
    float *X;
    int *ctr;
    cudaGetSymbolAddress((void**)&inph, g_inph);
    cudaGetSymbolAddress((void**)&embs, g_embs);
    cudaGetSymbolAddress((void**)&X,    g_X);
    cudaGetSymbolAddress((void**)&H0,   g_H0);
    cudaGetSymbolAddress((void**)&H1,   g_H1);
    cudaGetSymbolAddress((void**)&embT, g_embT);
    cudaGetSymbolAddress((void**)&w0xT, g_w0xT);
    cudaGetSymbolAddress((void**)&w0hT, g_w0hT);
    cudaGetSymbolAddress((void**)&w1xT, g_w1xT);
    cudaGetSymbolAddress((void**)&w1hT, g_w1hT);
    cudaGetSymbolAddress((void**)&owT,  g_owT);
    cudaGetSymbolAddress((void**)&ctr,  g_ctr);

    cudaFuncSetAttribute(lstm_layer,     cudaFuncAttributeMaxDynamicSharedMemorySize, LSTM_SMEM);
    cudaFuncSetAttribute(gemm16<float>,  cudaFuncAttributeMaxDynamicSharedMemorySize, GEMM_SMEM);
    cudaFuncSetAttribute(gemm16<__half>, cudaFuncAttributeMaxDynamicSharedMemorySize, GEMM_SMEM);

    // prep
    f2h_kernel<<<1024, 256>>>(inputs, inph, TB * VV);
    {
        dim3 blk(32, 8);
        transpose_cvt<<<dim3(VV/32, EE/32), blk>>>(emb,                EE, embT, VV, EE);
        transpose_cvt<<<dim3(EE/32, G4/32), blk>>>(w0,                 G4, w0xT, EE, G4);
        transpose_cvt<<<dim3(NH/32, G4/32), blk>>>(w0 + (size_t)EE*G4, G4, w0hT, NH, G4);
        transpose_cvt<<<dim3(NH/32, G4/32), blk>>>(w1,                 G4, w1xT, NH, G4);
        transpose_cvt<<<dim3(NH/32, G4/32), blk>>>(w1 + (size_t)NH*G4, G4, w1hT, NH, G4);
        transpose_cvt<<<dim3(NH/32, VV/32), blk>>>(outw,               VV, owT,  NH, VV);
    }
    zero_i<<<1, 32>>>(ctr);

    // embs = inputs @ emb
    gemm16<__half><<<dim3(EE/128, TB/128), 256, GEMM_SMEM>>>(inph, VV, embT, embs, EE, nullptr, TB, EE, VV);
    // X = embs @ W0x + b0
    gemm16<float><<<dim3(G4/128, TB/128), 256, GEMM_SMEM>>>(embs, EE, w0xT, X, G4, b0, TB, G4, EE);
    // layer 0 (persistent)
    lstm_layer<<<128, 256, LSTM_SMEM>>>(w0hT, X, H0, ctr);
    // X = H0 @ W1x + b1
    gemm16<float><<<dim3(G4/128, TB/128), 256, GEMM_SMEM>>>(H0, NH, w1xT, X, G4, b1, TB, G4, NH);
    // layer 1 (persistent)
    lstm_layer<<<128, 256, LSTM_SMEM>>>(w1hT, X, H1, ctr + 1);
    // logits = H1 @ out_w + out_b
    gemm16<float><<<dim3(VV/128, TB/128), 256, GEMM_SMEM>>>(H1, NH, owT, out, VV, outb, TB, VV, NH);
}

// round 9
// speedup vs baseline: 1.6961x; 1.0163x over previous
#include <cuda_runtime.h>
#include <cuda_fp16.h>
#include <stdint.h>

#define TT 256
#define BB 128
#define VV 256
#define EE 512
#define NH 1024
#define TB (TT*BB)          // 32768
#define G4 (4*NH)           // 4096

// ---------------- static device scratch ----------------
__device__ __align__(16) __half g_inph[(size_t)TB*VV];
__device__ __align__(16) __half g_embs[(size_t)TB*EE];
__device__ __align__(16) float  g_X[(size_t)TB*G4];
__device__ __align__(16) __half g_H0[(size_t)TB*NH];
__device__ __align__(16) __half g_H1[(size_t)TB*NH];
__device__ __align__(16) __half g_embT[EE*VV];           // [512][256]
__device__ __align__(16) __half g_w0xT[(size_t)G4*EE];   // [4096][512]
__device__ __align__(16) __half g_w0hT[(size_t)G4*NH];   // [4096][1024]
__device__ __align__(16) __half g_w1xT[(size_t)G4*NH];   // [4096][1024]
__device__ __align__(16) __half g_w1hT[(size_t)G4*NH];   // [4096][1024]
__device__ __align__(16) __half g_owT[VV*NH];            // [256][1024]
__device__ int g_ctr[2];

// ---------------- helpers ----------------
__device__ __forceinline__ void mma16(float d[4], const unsigned a[4], const unsigned b[2]) {
    asm volatile(
        "mma.sync.aligned.m16n8k16.row.col.f32.f16.f16.f32 "
        "{%0,%1,%2,%3}, {%4,%5,%6,%7}, {%8,%9}, {%0,%1,%2,%3};\n"
        : "+f"(d[0]), "+f"(d[1]), "+f"(d[2]), "+f"(d[3])
        : "r"(a[0]), "r"(a[1]), "r"(a[2]), "r"(a[3]), "r"(b[0]), "r"(b[1]));
}
__device__ __forceinline__ void ldsm_x4(unsigned r[4], const __half* p) {
    unsigned a = (unsigned)__cvta_generic_to_shared(p);
    asm volatile("ldmatrix.sync.aligned.m8n8.x4.shared.b16 {%0,%1,%2,%3}, [%4];\n"
        : "=r"(r[0]), "=r"(r[1]), "=r"(r[2]), "=r"(r[3]) : "r"(a));
}
__device__ __forceinline__ void cpa16(__half* dst, const __half* src) {
    unsigned d = (unsigned)__cvta_generic_to_shared(dst);
    asm volatile("cp.async.cg.shared.global [%0], [%1], 16;\n" :: "r"(d), "l"(src));
}
#define CPA_COMMIT() asm volatile("cp.async.commit_group;\n" ::: "memory")
template <int N> __device__ __forceinline__ void cpa_wait() {
    asm volatile("cp.async.wait_group %0;\n" :: "n"(N) : "memory");
}
__device__ __forceinline__ void cstore2(float* C, size_t i, float a, float b) {
    *(float2*)&C[i] = make_float2(a, b);
}
__device__ __forceinline__ void cstore2(__half* C, size_t i, float a, float b) {
    *(__half2*)&C[i] = __floats2half2_rn(a, b);
}
__device__ __forceinline__ float sigf(float x) { return 1.f / (1.f + __expf(-x)); }

__global__ void zero_i(int* p) { if (threadIdx.x < 2) p[threadIdx.x] = 0; }
__global__ void f2h_kernel(const float* __restrict__ s, __half* __restrict__ d, int n) {
    for (int i = blockIdx.x * blockDim.x + threadIdx.x; i < n; i += gridDim.x * blockDim.x)
        d[i] = __float2half(s[i]);
}
// src fp32 [K][N] (row stride lds) -> dst fp16 [N][K]
__global__ void transpose_cvt(const float* __restrict__ src, int lds,
                              __half* __restrict__ dst, int K, int N) {
    __shared__ float tile[32][33];
    int kb = blockIdx.x * 32, nb = blockIdx.y * 32;
    #pragma unroll
    for (int i = threadIdx.y; i < 32; i += 8) {
        int k = kb + i, n = nb + threadIdx.x;
        tile[i][threadIdx.x] = (k < K && n < N) ? src[(size_t)k * lds + n] : 0.f;
    }
    __syncthreads();
    #pragma unroll
    for (int i = threadIdx.y; i < 32; i += 8) {
        int n = nb + i, k = kb + threadIdx.x;
        if (n < N && k < K) dst[(size_t)n * K + k] = __float2half(tile[threadIdx.x][i]);
    }
}

// ---------------- fp16 GEMM (validated R7): C = A @ Bt^T (+bias), 128x128 tile ----------------
#define GAST (128*40)
#define GBST (128*40)
#define GEMM_SMEM ((4*(GAST+GBST))*2)

template <typename TOUT>
__global__ void __launch_bounds__(256, 2) gemm16(
    const __half* __restrict__ A, int lda,
    const __half* __restrict__ Bt,
    TOUT* __restrict__ C, int ldc,
    const float* __restrict__ bias,
    int M, int N, int K)
{
    extern __shared__ __half sm[];
    __half* As = sm;
    __half* Bs = sm + 4*GAST;

    const int tid = threadIdx.x;
    const int bm = blockIdx.y * 128, bn = blockIdx.x * 128;
    const int wid = tid >> 5, lane = tid & 31;
    const int wr = (wid & 1) * 64, wc = (wid >> 1) * 32;
    const int r = lane >> 2, cl = lane & 3;

    float acc[4][4][4];
    #pragma unroll
    for (int i = 0; i < 4; ++i)
        #pragma unroll
        for (int j = 0; j < 4; ++j)
            #pragma unroll
            for (int k = 0; k < 4; ++k) acc[i][j][k] = 0.f;

    auto loadG = [&](int s, int kt) {
        #pragma unroll
        for (int i = 0; i < 2; ++i) {
            int idx = tid + i * 256;
            int row = idx >> 2, cc = idx & 3;
            cpa16(As + s*GAST + row*40 + cc*8,
                  A + (size_t)(bm + row) * lda + kt*32 + cc*8);
            cpa16(Bs + s*GBST + row*40 + cc*8,
                  Bt + (size_t)(bn + row) * K + kt*32 + cc*8);
        }
    };

    const int ktiles = K >> 5;
    #pragma unroll
    for (int s = 0; s < 3; ++s) { if (s < ktiles) loadG(s, s); CPA_COMMIT(); }

    const int a_row = (lane & 15);
    const int a_col = (lane >> 4) << 3;
    const int b_row = (lane & 7) + ((lane >> 4) << 3);
    const int b_col = (lane & 8);

    for (int kt = 0; kt < ktiles; ++kt) {
        cpa_wait<2>();
        __syncthreads();
        if (kt + 3 < ktiles) loadG((kt + 3) & 3, kt + 3);
        CPA_COMMIT();

        const __half* sA = As + (kt & 3) * GAST;
        const __half* sB = Bs + (kt & 3) * GBST;
        #pragma unroll
        for (int ks = 0; ks < 2; ++ks) {
            const int k0 = ks * 16;
            unsigned af[4][4], bf01[4], bf23[4];
            #pragma unroll
            for (int mt = 0; mt < 4; ++mt)
                ldsm_x4(af[mt], sA + (wr + mt*16 + a_row)*40 + k0 + a_col);
            ldsm_x4(bf01, sB + (wc      + b_row)*40 + k0 + b_col);
            ldsm_x4(bf23, sB + (wc + 16 + b_row)*40 + k0 + b_col);
            #pragma unroll
            for (int mt = 0; mt < 4; ++mt) {
                mma16(acc[mt][0], af[mt], bf01 + 0);
                mma16(acc[mt][1], af[mt], bf01 + 2);
                mma16(acc[mt][2], af[mt], bf23 + 0);
                mma16(acc[mt][3], af[mt], bf23 + 2);
            }
        }
    }

    #pragma unroll
    for (int mt = 0; mt < 4; ++mt)
        #pragma unroll
        for (int nt = 0; nt < 4; ++nt) {
            const int row = bm + wr + mt*16 + r;
            const int col = bn + wc + nt*8 + 2*cl;
            const float b0 = bias ? bias[col]     : 0.f;
            const float b1 = bias ? bias[col + 1] : 0.f;
            cstore2(C, (size_t)row * ldc + col,       acc[mt][nt][0] + b0, acc[mt][nt][1] + b1);
            cstore2(C, (size_t)(row + 8) * ldc + col, acc[mt][nt][2] + b0, acc[mt][nt][3] + b1);
        }
}

// ---------------- persistent LSTM layer kernel (R7 + backoff spin + X smem staging) ----------------
// 128 CTAs (1/SM). CTA bx owns hidden cols [bx*8, bx*8+8) of all 4 gates
// (GEMM N=32 = 4 gates x 8 cols, K=1024). W_h slice (64KB) resident in smem.
// 8 warps, each mma over 16 rows x 32 cols; direct LDS fragment loads.
// Sync: global atomic counter + one-address spin with nanosleep backoff.
#define AST (128*72)
#define XS_OFF ((32*1032 + 4*AST)*2)          // byte offset of X stage (fp32 [128][36])
#define LSTM_SMEM (XS_OFF + 128*36*4)

__global__ void __launch_bounds__(256, 1) lstm_layer(
    const __half* __restrict__ WhT,    // [4096][1024]
    const float*  __restrict__ X,      // [T*128][4096]
    __half* __restrict__ H,            // [T*128][1024]
    int* __restrict__ ctr)
{
    extern __shared__ __half sm[];
    __half* Bs = sm;                   // 32 x 1032 (n = gate*8+j, k = 0..1023)
    __half* As = sm + 32*1032;         // 4 stages x 128 x 72
    float*  Xs = (float*)((char*)sm + XS_OFF);   // 128 x 36 fp32

    const int tid = threadIdx.x, lane = tid & 31, wid = tid >> 5;
    const int r = lane >> 2, cl = lane & 3;
    const int bx = blockIdx.x;
    const int wr = wid * 16;
    const int row0 = wr + r, row1 = row0 + 8;
    const int jj = 2 * cl;
    const int colg = bx * 8 + jj;

    // load W_h slice once: rows g*1024 + bx*8 + j  ->  Bs[g*8+j][0..1023]
    #pragma unroll
    for (int i = 0; i < 16; ++i) {
        int idx = tid + i * 256;            // 0..4095
        int n = idx >> 7, cc = idx & 127;
        int g = n >> 3, j = n & 7;
        cpa16(Bs + n*1032 + cc*8,
              WhT + (size_t)(g*1024 + bx*8 + j) * 1024 + cc*8);
    }
    CPA_COMMIT();
    cpa_wait<0>();
    __syncthreads();

    float c0 = 0.f, c1 = 0.f, c2 = 0.f, c3 = 0.f;

    auto loadA = [&](__half* dst, const __half* hsrc, int kt) {
        #pragma unroll
        for (int i = 0; i < 4; ++i) {
            int idx = tid + i * 256;        // 0..1023
            int row = idx >> 3, cc = idx & 7;
            cpa16(dst + row*72 + cc*8, hsrc + (size_t)row*1024 + kt*64 + cc*8);
        }
    };
    // stage this step's X gate block [128 rows][4 gates x 8 cols] into smem
    auto loadX = [&](const float* Xt) {
        #pragma unroll
        for (int i = 0; i < 4; ++i) {
            int u = tid + i * 256;          // 0..1023 (16B granules)
            int row = u >> 3, seg = u & 7;  // seg = gate*2 + half
            int g = seg >> 1, hf = seg & 1;
            cpa16((__half*)(Xs + row*36 + g*8 + hf*4),
                  (const __half*)(Xt + (size_t)row*4096 + g*1024 + bx*8 + hf*4));
        }
    };

    for (int t = 0; t < TT; ++t) {
        float acc[4][4];
        #pragma unroll
        for (int i = 0; i < 4; ++i)
            #pragma unroll
            for (int j = 0; j < 4; ++j) acc[i][j] = 0.f;

        const float* Xt = X + (size_t)t * (BB * G4);

        if (t > 0) {
            const __half* hsrc = H + (size_t)(t - 1) * BB * NH;
            // group 0 = A chunk 0 + X stage (X lands with chunk 0, read in epilogue)
            loadA(As + 0*AST, hsrc, 0); loadX(Xt); CPA_COMMIT();
            loadA(As + 1*AST, hsrc, 1); CPA_COMMIT();
            loadA(As + 2*AST, hsrc, 2); CPA_COMMIT();

            #pragma unroll 1
            for (int kt = 0; kt < 16; ++kt) {
                cpa_wait<2>();
                __syncthreads();
                if (kt + 3 < 16) loadA(As + ((kt + 3) & 3) * AST, hsrc, kt + 3);
                CPA_COMMIT();

                const __half* sA = As + (kt & 3) * AST;
                #pragma unroll
                for (int ks = 0; ks < 4; ++ks) {
                    const int k0 = ks * 16;
                    unsigned af[4];
                    af[0] = *(const unsigned*)&sA[row0*72 + k0 + jj];
                    af[1] = *(const unsigned*)&sA[row1*72 + k0 + jj];
                    af[2] = *(const unsigned*)&sA[row0*72 + k0 + jj + 8];
                    af[3] = *(const unsigned*)&sA[row1*72 + k0 + jj + 8];
                    #pragma unroll
                    for (int nt = 0; nt < 4; ++nt) {
                        const __half* bp = Bs + (size_t)(nt*8 + r)*1032 + kt*64 + k0 + jj;
                        unsigned bf[2];
                        bf[0] = *(const unsigned*)bp;
                        bf[1] = *(const unsigned*)(bp + 8);
                        mma16(acc[nt], af, bf);
                    }
                }
            }
        }

        // gates + state update, all in registers
        // X source: smem stage when t>0 (landed with chunk 0), global at t=0
        const float* xa = (t > 0) ? (Xs + row0*36 + jj) : (Xt + (size_t)row0 * 4096 + colg);
        const float* xb = (t > 0) ? (Xs + row1*36 + jj) : (Xt + (size_t)row1 * 4096 + colg);
        const int gs = (t > 0) ? 8 : 1024;
        {
            float2 xf = *(const float2*)(xa);
            float2 xi = *(const float2*)(xa + gs);
            float2 xo = *(const float2*)(xa + 2*gs);
            float2 xg = *(const float2*)(xa + 3*gs);
            float f  = sigf(acc[0][0] + xf.x), ig  = sigf(acc[1][0] + xi.x);
            float o  = sigf(acc[2][0] + xo.x), gg  = tanhf(acc[3][0] + xg.x);
            c0 = f * c0 + ig * gg;
            float f1 = sigf(acc[0][1] + xf.y), ig1 = sigf(acc[1][1] + xi.y);
            float o1 = sigf(acc[2][1] + xo.y), gg1 = tanhf(acc[3][1] + xg.y);
            c1 = f1 * c1 + ig1 * gg1;
            __half2 hv = __floats2half2_rn(o * tanhf(c0), o1 * tanhf(c1));
            *(__half2*)&H[(size_t)t*BB*NH + (size_t)row0*1024 + colg] = hv;
        }
        {
            float2 xf = *(const float2*)(xb);
            float2 xi = *(const float2*)(xb + gs);
            float2 xo = *(const float2*)(xb + 2*gs);
            float2 xg = *(const float2*)(xb + 3*gs);
            float f  = sigf(acc[0][2] + xf.x), ig  = sigf(acc[1][2] + xi.x);
            float o  = sigf(acc[2][2] + xo.x), gg  = tanhf(acc[3][2] + xg.x);
            c2 = f * c2 + ig * gg;
            float f1 = sigf(acc[0][3] + xf.y), ig1 = sigf(acc[1][3] + xi.y);
            float o1 = sigf(acc[2][3] + xo.y), gg1 = tanhf(acc[3][3] + xg.y);
            c3 = f1 * c3 + ig1 * gg1;
            __half2 hv = __floats2half2_rn(o * tanhf(c2), o1 * tanhf(c3));
            *(__half2*)&H[(size_t)t*BB*NH + (size_t)row1*1024 + colg] = hv;
        }

        if (t + 1 < TT) {
            __threadfence();       // release h stores GPU-wide
            __syncthreads();       // all threads' stores fenced before arrive
            if (tid == 0) {
                atomicAdd(ctr, 1);
                const int target = 128 * (t + 1);
                int v;
                while (true) {
                    asm volatile("ld.acquire.gpu.b32 %0, [%1];" : "=r"(v) : "l"(ctr));
                    if (v >= target) break;
                    __nanosleep(64);   // backoff: avoid LTS same-line poll storm
                }
            }
            __syncthreads();       // broadcast acquire to whole CTA
        }
    }
}

// ---------------- launch ----------------
extern "C" void kernel_launch(void* const* d_in, const int* in_sizes, int n_in,
                              void* d_out, int out_size) {
    (void)in_sizes; (void)n_in; (void)out_size;
    const float* inputs = (const float*)d_in[0];
    const float* emb    = (const float*)d_in[1];
    const float* w0     = (const float*)d_in[2];
    const float* b0     = (const float*)d_in[3];
    const float* w1     = (const float*)d_in[4];
    const float* b1     = (const float*)d_in[5];
    const float* outw   = (const float*)d_in[6];
    const float* outb   = (const float*)d_in[7];
    float* out = (float*)d_out;

    __half *inph, *embs, *H0, *H1, *embT, *w0xT, *w0hT, *w1xT, *w1hT, *owT;
    float *X;
    int *ctr;
    cudaGetSymbolAddress((void**)&inph, g_inph);
    cudaGetSymbolAddress((void**)&embs, g_embs);
    cudaGetSymbolAddress((void**)&X,    g_X);
    cudaGetSymbolAddress((void**)&H0,   g_H0);
    cudaGetSymbolAddress((void**)&H1,   g_H1);
    cudaGetSymbolAddress((void**)&embT, g_embT);
    cudaGetSymbolAddress((void**)&w0xT, g_w0xT);
    cudaGetSymbolAddress((void**)&w0hT, g_w0hT);
    cudaGetSymbolAddress((void**)&w1xT, g_w1xT);
    cudaGetSymbolAddress((void**)&w1hT, g_w1hT);
    cudaGetSymbolAddress((void**)&owT,  g_owT);
    cudaGetSymbolAddress((void**)&ctr,  g_ctr);

    cudaFuncSetAttribute(lstm_layer,     cudaFuncAttributeMaxDynamicSharedMemorySize, LSTM_SMEM);
    cudaFuncSetAttribute(gemm16<float>,  cudaFuncAttributeMaxDynamicSharedMemorySize, GEMM_SMEM);
    cudaFuncSetAttribute(gemm16<__half>, cudaFuncAttributeMaxDynamicSharedMemorySize, GEMM_SMEM);

    // prep
    f2h_kernel<<<1024, 256>>>(inputs, inph, TB * VV);
    {
        dim3 blk(32, 8);
        transpose_cvt<<<dim3(VV/32, EE/32), blk>>>(emb,                EE, embT, VV, EE);
        transpose_cvt<<<dim3(EE/32, G4/32), blk>>>(w0,                 G4, w0xT, EE, G4);
        transpose_cvt<<<dim3(NH/32, G4/32), blk>>>(w0 + (size_t)EE*G4, G4, w0hT, NH, G4);
        transpose_cvt<<<dim3(NH/32, G4/32), blk>>>(w1,                 G4, w1xT, NH, G4);
        transpose_cvt<<<dim3(NH/32, G4/32), blk>>>(w1 + (size_t)NH*G4, G4, w1hT, NH, G4);
        transpose_cvt<<<dim3(NH/32, VV/32), blk>>>(outw,               VV, owT,  NH, VV);
    }
    zero_i<<<1, 32>>>(ctr);

    // embs = inputs @ emb
    gemm16<__half><<<dim3(EE/128, TB/128), 256, GEMM_SMEM>>>(inph, VV, embT, embs, EE, nullptr, TB, EE, VV);
    // X = embs @ W0x + b0
    gemm16<float><<<dim3(G4/128, TB/128), 256, GEMM_SMEM>>>(embs, EE, w0xT, X, G4, b0, TB, G4, EE);
    // layer 0 (persistent)
    lstm_layer<<<128, 256, LSTM_SMEM>>>(w0hT, X, H0, ctr);
    // X = H0 @ W1x + b1
    gemm16<float><<<dim3(G4/128, TB/128), 256, GEMM_SMEM>>>(H0, NH, w1xT, X, G4, b1, TB, G4, NH);
    // layer 1 (persistent)
    lstm_layer<<<128, 256, LSTM_SMEM>>>(w1hT, X, H1, ctr + 1);
    // logits = H1 @ out_w + out_b
    gemm16<float><<<dim3(VV/128, TB/128), 256, GEMM_SMEM>>>(H1, NH, owT, out, VV, outb, TB, VV, NH);
}

// round 10
// speedup vs baseline: 1.7885x; 1.0545x over previous
#include <cuda_runtime.h>
#include <cuda_fp16.h>
#include <stdint.h>

#define TT 256
#define BB 128
#define VV 256
#define EE 512
#define NH 1024
#define TB (TT*BB)          // 32768
#define G4 (4*NH)           // 4096

// ---------------- static device scratch ----------------
__device__ __align__(16) __half g_inph[(size_t)TB*VV];
__device__ __align__(16) __half g_embs[(size_t)TB*EE];
__device__ __align__(16) float  g_X[(size_t)TB*G4];
__device__ __align__(16) __half g_H0[(size_t)TB*NH];
__device__ __align__(16) __half g_H1[(size_t)TB*NH];
__device__ __align__(16) __half g_embT[EE*VV];           // [512][256]
__device__ __align__(16) __half g_w0xT[(size_t)G4*EE];   // [4096][512]
__device__ __align__(16) __half g_w0hT[(size_t)G4*NH];   // [4096][1024]
__device__ __align__(16) __half g_w1xT[(size_t)G4*NH];   // [4096][1024]
__device__ __align__(16) __half g_w1hT[(size_t)G4*NH];   // [4096][1024]
__device__ __align__(16) __half g_owT[VV*NH];            // [256][1024]
__device__ int g_ctr[2];

// ---------------- helpers ----------------
__device__ __forceinline__ void mma16(float d[4], const unsigned a[4], const unsigned b[2]) {
    asm volatile(
        "mma.sync.aligned.m16n8k16.row.col.f32.f16.f16.f32 "
        "{%0,%1,%2,%3}, {%4,%5,%6,%7}, {%8,%9}, {%0,%1,%2,%3};\n"
        : "+f"(d[0]), "+f"(d[1]), "+f"(d[2]), "+f"(d[3])
        : "r"(a[0]), "r"(a[1]), "r"(a[2]), "r"(a[3]), "r"(b[0]), "r"(b[1]));
}
__device__ __forceinline__ void ldsm_x4(unsigned r[4], const __half* p) {
    unsigned a = (unsigned)__cvta_generic_to_shared(p);
    asm volatile("ldmatrix.sync.aligned.m8n8.x4.shared.b16 {%0,%1,%2,%3}, [%4];\n"
        : "=r"(r[0]), "=r"(r[1]), "=r"(r[2]), "=r"(r[3]) : "r"(a));
}
__device__ __forceinline__ void cpa16(__half* dst, const __half* src) {
    unsigned d = (unsigned)__cvta_generic_to_shared(dst);
    asm volatile("cp.async.cg.shared.global [%0], [%1], 16;\n" :: "r"(d), "l"(src));
}
#define CPA_COMMIT() asm volatile("cp.async.commit_group;\n" ::: "memory")
template <int N> __device__ __forceinline__ void cpa_wait() {
    asm volatile("cp.async.wait_group %0;\n" :: "n"(N) : "memory");
}
__device__ __forceinline__ void cstore2(float* C, size_t i, float a, float b) {
    *(float2*)&C[i] = make_float2(a, b);
}
__device__ __forceinline__ void cstore2(__half* C, size_t i, float a, float b) {
    *(__half2*)&C[i] = __floats2half2_rn(a, b);
}
__device__ __forceinline__ float sigf(float x) { return 1.f / (1.f + __expf(-x)); }

__global__ void zero_i(int* p) { if (threadIdx.x < 2) p[threadIdx.x] = 0; }
__global__ void f2h_kernel(const float* __restrict__ s, __half* __restrict__ d, int n) {
    for (int i = blockIdx.x * blockDim.x + threadIdx.x; i < n; i += gridDim.x * blockDim.x)
        d[i] = __float2half(s[i]);
}
// src fp32 [K][N] (row stride lds) -> dst fp16 [N][K]
__global__ void transpose_cvt(const float* __restrict__ src, int lds,
                              __half* __restrict__ dst, int K, int N) {
    __shared__ float tile[32][33];
    int kb = blockIdx.x * 32, nb = blockIdx.y * 32;
    #pragma unroll
    for (int i = threadIdx.y; i < 32; i += 8) {
        int k = kb + i, n = nb + threadIdx.x;
        tile[i][threadIdx.x] = (k < K && n < N) ? src[(size_t)k * lds + n] : 0.f;
    }
    __syncthreads();
    #pragma unroll
    for (int i = threadIdx.y; i < 32; i += 8) {
        int n = nb + i, k = kb + threadIdx.x;
        if (n < N && k < K) dst[(size_t)n * K + k] = __float2half(tile[threadIdx.x][i]);
    }
}

// ---------------- fp16 GEMM (validated R7): C = A @ Bt^T (+bias), 128x128 tile ----------------
#define GAST (128*40)
#define GBST (128*40)
#define GEMM_SMEM ((4*(GAST+GBST))*2)

template <typename TOUT>
__global__ void __launch_bounds__(256, 2) gemm16(
    const __half* __restrict__ A, int lda,
    const __half* __restrict__ Bt,
    TOUT* __restrict__ C, int ldc,
    const float* __restrict__ bias,
    int M, int N, int K)
{
    extern __shared__ __half sm[];
    __half* As = sm;
    __half* Bs = sm + 4*GAST;

    const int tid = threadIdx.x;
    const int bm = blockIdx.y * 128, bn = blockIdx.x * 128;
    const int wid = tid >> 5, lane = tid & 31;
    const int wr = (wid & 1) * 64, wc = (wid >> 1) * 32;
    const int r = lane >> 2, cl = lane & 3;

    float acc[4][4][4];
    #pragma unroll
    for (int i = 0; i < 4; ++i)
        #pragma unroll
        for (int j = 0; j < 4; ++j)
            #pragma unroll
            for (int k = 0; k < 4; ++k) acc[i][j][k] = 0.f;

    auto loadG = [&](int s, int kt) {
        #pragma unroll
        for (int i = 0; i < 2; ++i) {
            int idx = tid + i * 256;
            int row = idx >> 2, cc = idx & 3;
            cpa16(As + s*GAST + row*40 + cc*8,
                  A + (size_t)(bm + row) * lda + kt*32 + cc*8);
            cpa16(Bs + s*GBST + row*40 + cc*8,
                  Bt + (size_t)(bn + row) * K + kt*32 + cc*8);
        }
    };

    const int ktiles = K >> 5;
    #pragma unroll
    for (int s = 0; s < 3; ++s) { if (s < ktiles) loadG(s, s); CPA_COMMIT(); }

    const int a_row = (lane & 15);
    const int a_col = (lane >> 4) << 3;
    const int b_row = (lane & 7) + ((lane >> 4) << 3);
    const int b_col = (lane & 8);

    for (int kt = 0; kt < ktiles; ++kt) {
        cpa_wait<2>();
        __syncthreads();
        if (kt + 3 < ktiles) loadG((kt + 3) & 3, kt + 3);
        CPA_COMMIT();

        const __half* sA = As + (kt & 3) * GAST;
        const __half* sB = Bs + (kt & 3) * GBST;
        #pragma unroll
        for (int ks = 0; ks < 2; ++ks) {
            const int k0 = ks * 16;
            unsigned af[4][4], bf01[4], bf23[4];
            #pragma unroll
            for (int mt = 0; mt < 4; ++mt)
                ldsm_x4(af[mt], sA + (wr + mt*16 + a_row)*40 + k0 + a_col);
            ldsm_x4(bf01, sB + (wc      + b_row)*40 + k0 + b_col);
            ldsm_x4(bf23, sB + (wc + 16 + b_row)*40 + k0 + b_col);
            #pragma unroll
            for (int mt = 0; mt < 4; ++mt) {
                mma16(acc[mt][0], af[mt], bf01 + 0);
                mma16(acc[mt][1], af[mt], bf01 + 2);
                mma16(acc[mt][2], af[mt], bf23 + 0);
                mma16(acc[mt][3], af[mt], bf23 + 2);
            }
        }
    }

    #pragma unroll
    for (int mt = 0; mt < 4; ++mt)
        #pragma unroll
        for (int nt = 0; nt < 4; ++nt) {
            const int row = bm + wr + mt*16 + r;
            const int col = bn + wc + nt*8 + 2*cl;
            const float b0 = bias ? bias[col]     : 0.f;
            const float b1 = bias ? bias[col + 1] : 0.f;
            cstore2(C, (size_t)row * ldc + col,       acc[mt][nt][0] + b0, acc[mt][nt][1] + b1);
            cstore2(C, (size_t)(row + 8) * ldc + col, acc[mt][nt][2] + b0, acc[mt][nt][3] + b1);
        }
}

// ---------------- persistent LSTM layer kernel ----------------
// 128 CTAs (1/SM). CTA bx owns hidden cols [bx*8, bx*8+8) of all 4 gates
// (GEMM N=32, K=1024). W_h slice (64KB) resident in smem.
// 8 warps, each mma over 16 rows x 32 cols; direct LDS fragment loads.
// K-chunk 128 halfs: 8 pipeline rounds/step (3-stage ring).
// Sync: counter + release-reduction (no membar.gl) + backoff acquire spin.
#define BST  (32*1032)
#define AST2 (128*136)
#define XS_OFF ((BST + 3*AST2)*2)             // byte offset of X stage (fp32 [128][36])
#define LSTM_SMEM (XS_OFF + 128*36*4)

__global__ void __launch_bounds__(256, 1) lstm_layer(
    const __half* __restrict__ WhT,    // [4096][1024]
    const float*  __restrict__ X,      // [T*128][4096]
    __half* __restrict__ H,            // [T*128][1024]
    int* __restrict__ ctr)
{
    extern __shared__ __half sm[];
    __half* Bs = sm;                   // 32 x 1032 (n = gate*8+j, k = 0..1023)
    __half* As = sm + BST;             // 3 stages x 128 x 136
    float*  Xs = (float*)((char*)sm + XS_OFF);   // 128 x 36 fp32

    const int tid = threadIdx.x, lane = tid & 31, wid = tid >> 5;
    const int r = lane >> 2, cl = lane & 3;
    const int bx = blockIdx.x;
    const int wr = wid * 16;
    const int row0 = wr + r, row1 = row0 + 8;
    const int jj = 2 * cl;
    const int colg = bx * 8 + jj;

    // load W_h slice once: rows g*1024 + bx*8 + j  ->  Bs[g*8+j][0..1023]
    #pragma unroll
    for (int i = 0; i < 16; ++i) {
        int idx = tid + i * 256;            // 0..4095
        int n = idx >> 7, cc = idx & 127;
        int g = n >> 3, j = n & 7;
        cpa16(Bs + n*1032 + cc*8,
              WhT + (size_t)(g*1024 + bx*8 + j) * 1024 + cc*8);
    }
    CPA_COMMIT();
    cpa_wait<0>();
    __syncthreads();

    float c0 = 0.f, c1 = 0.f, c2 = 0.f, c3 = 0.f;

    // A chunk: 128 rows x 128 halfs of k (32KB), row stride 136 halfs
    auto loadA = [&](__half* dst, const __half* hsrc, int ch) {
        #pragma unroll
        for (int i = 0; i < 8; ++i) {
            int idx = tid + i * 256;        // 0..2047 (16B units)
            int row = idx >> 4, cc = idx & 15;
            cpa16(dst + row*136 + cc*8, hsrc + (size_t)row*1024 + ch*128 + cc*8);
        }
    };
    // stage this step's X gate block [128 rows][4 gates x 8 cols] into smem
    auto loadX = [&](const float* Xt) {
        #pragma unroll
        for (int i = 0; i < 4; ++i) {
            int u = tid + i * 256;          // 0..1023 (16B granules)
            int row = u >> 3, seg = u & 7;  // seg = gate*2 + half
            int g = seg >> 1, hf = seg & 1;
            cpa16((__half*)(Xs + row*36 + g*8 + hf*4),
                  (const __half*)(Xt + (size_t)row*4096 + g*1024 + bx*8 + hf*4));
        }
    };

    for (int t = 0; t < TT; ++t) {
        float acc[4][4];
        #pragma unroll
        for (int i = 0; i < 4; ++i)
            #pragma unroll
            for (int j = 0; j < 4; ++j) acc[i][j] = 0.f;

        const float* Xt = X + (size_t)t * (BB * G4);

        if (t > 0) {
            const __half* hsrc = H + (size_t)(t - 1) * BB * NH;
            loadA(As + 0*AST2, hsrc, 0); loadX(Xt); CPA_COMMIT();
            loadA(As + 1*AST2, hsrc, 1); CPA_COMMIT();

            #pragma unroll 1
            for (int kt = 0; kt < 8; ++kt) {
                cpa_wait<1>();
                __syncthreads();
                if (kt + 2 < 8) {
                    int st = kt + 2; st -= (st >= 3) ? 3 : 0; st -= (st >= 3) ? 3 : 0;
                    loadA(As + st * AST2, hsrc, kt + 2);
                }
                CPA_COMMIT();

                int sb = kt; sb -= (sb >= 3) ? 3 : 0; sb -= (sb >= 3) ? 3 : 0;
                const __half* sA = As + sb * AST2;
                #pragma unroll
                for (int ks = 0; ks < 8; ++ks) {
                    const int k0 = ks * 16;
                    unsigned af[4];
                    af[0] = *(const unsigned*)&sA[row0*136 + k0 + jj];
                    af[1] = *(const unsigned*)&sA[row1*136 + k0 + jj];
                    af[2] = *(const unsigned*)&sA[row0*136 + k0 + jj + 8];
                    af[3] = *(const unsigned*)&sA[row1*136 + k0 + jj + 8];
                    #pragma unroll
                    for (int nt = 0; nt < 4; ++nt) {
                        const __half* bp = Bs + (size_t)(nt*8 + r)*1032 + kt*128 + k0 + jj;
                        unsigned bf[2];
                        bf[0] = *(const unsigned*)bp;
                        bf[1] = *(const unsigned*)(bp + 8);
                        mma16(acc[nt], af, bf);
                    }
                }
            }
        }

        // gates + state update, all in registers
        // X source: smem stage when t>0 (landed with chunk 0), global at t=0
        const float* xa = (t > 0) ? (Xs + row0*36 + jj) : (Xt + (size_t)row0 * 4096 + colg);
        const float* xb = (t > 0) ? (Xs + row1*36 + jj) : (Xt + (size_t)row1 * 4096 + colg);
        const int gs = (t > 0) ? 8 : 1024;
        {
            float2 xf = *(const float2*)(xa);
            float2 xi = *(const float2*)(xa + gs);
            float2 xo = *(const float2*)(xa + 2*gs);
            float2 xg = *(const float2*)(xa + 3*gs);
            float f  = sigf(acc[0][0] + xf.x), ig  = sigf(acc[1][0] + xi.x);
            float o  = sigf(acc[2][0] + xo.x), gg  = tanhf(acc[3][0] + xg.x);
            c0 = f * c0 + ig * gg;
            float f1 = sigf(acc[0][1] + xf.y), ig1 = sigf(acc[1][1] + xi.y);
            float o1 = sigf(acc[2][1] + xo.y), gg1 = tanhf(acc[3][1] + xg.y);
            c1 = f1 * c1 + ig1 * gg1;
            __half2 hv = __floats2half2_rn(o * tanhf(c0), o1 * tanhf(c1));
            *(__half2*)&H[(size_t)t*BB*NH + (size_t)row0*1024 + colg] = hv;
        }
        {
            float2 xf = *(const float2*)(xb);
            float2 xi = *(const float2*)(xb + gs);
            float2 xo = *(const float2*)(xb + 2*gs);
            float2 xg = *(const float2*)(xb + 3*gs);
            float f  = sigf(acc[0][2] + xf.x), ig  = sigf(acc[1][2] + xi.x);
            float o  = sigf(acc[2][2] + xo.x), gg  = tanhf(acc[3][2] + xg.x);
            c2 = f * c2 + ig * gg;
            float f1 = sigf(acc[0][3] + xf.y), ig1 = sigf(acc[1][3] + xi.y);
            float o1 = sigf(acc[2][3] + xo.y), gg1 = tanhf(acc[3][3] + xg.y);
            c3 = f1 * c3 + ig1 * gg1;
            __half2 hv = __floats2half2_rn(o * tanhf(c2), o1 * tanhf(c3));
            *(__half2*)&H[(size_t)t*BB*NH + (size_t)row1*1024 + colg] = hv;
        }

        if (t + 1 < TT) {
            __syncthreads();       // all CTA threads' H stores happen-before tid0's release
            if (tid == 0) {
                // release-reduction: orders prior (barrier-collected) stores, no membar.gl
                asm volatile("red.release.gpu.global.add.u32 [%0], %1;"
                             :: "l"(ctr), "r"(1) : "memory");
                const int target = 128 * (t + 1);
                int v;
                while (true) {
                    asm volatile("ld.acquire.gpu.b32 %0, [%1];" : "=r"(v) : "l"(ctr));
                    if (v >= target) break;
                    __nanosleep(64);   // backoff
                }
            }
            __syncthreads();       // broadcast acquire to whole CTA
        }
    }
}

// ---------------- launch ----------------
extern "C" void kernel_launch(void* const* d_in, const int* in_sizes, int n_in,
                              void* d_out, int out_size) {
    (void)in_sizes; (void)n_in; (void)out_size;
    const float* inputs = (const float*)d_in[0];
    const float* emb    = (const float*)d_in[1];
    const float* w0     = (const float*)d_in[2];
    const float* b0     = (const float*)d_in[3];
    const float* w1     = (const float*)d_in[4];
    const float* b1     = (const float*)d_in[5];
    const float* outw   = (const float*)d_in[6];
    const float* outb   = (const float*)d_in[7];
    float* out = (float*)d_out;

    __half *inph, *embs, *H0, *H1, *embT, *w0xT, *w0hT, *w1xT, *w1hT, *owT;
    float *X;
    int *ctr;
    cudaGetSymbolAddress((void**)&inph, g_inph);
    cudaGetSymbolAddress((void**)&embs, g_embs);
    cudaGetSymbolAddress((void**)&X,    g_X);
    cudaGetSymbolAddress((void**)&H0,   g_H0);
    cudaGetSymbolAddress((void**)&H1,   g_H1);
    cudaGetSymbolAddress((void**)&embT, g_embT);
    cudaGetSymbolAddress((void**)&w0xT, g_w0xT);
    cudaGetSymbolAddress((void**)&w0hT, g_w0hT);
    cudaGetSymbolAddress((void**)&w1xT, g_w1xT);
    cudaGetSymbolAddress((void**)&w1hT, g_w1hT);
    cudaGetSymbolAddress((void**)&owT,  g_owT);
    cudaGetSymbolAddress((void**)&ctr,  g_ctr);

    cudaFuncSetAttribute(lstm_layer,     cudaFuncAttributeMaxDynamicSharedMemorySize, LSTM_SMEM);
    cudaFuncSetAttribute(gemm16<float>,  cudaFuncAttributeMaxDynamicSharedMemorySize, GEMM_SMEM);
    cudaFuncSetAttribute(gemm16<__half>, cudaFuncAttributeMaxDynamicSharedMemorySize, GEMM_SMEM);

    // prep
    f2h_kernel<<<1024, 256>>>(inputs, inph, TB * VV);
    {
        dim3 blk(32, 8);
        transpose_cvt<<<dim3(VV/32, EE/32), blk>>>(emb,                EE, embT, VV, EE);
        transpose_cvt<<<dim3(EE/32, G4/32), blk>>>(w0,                 G4, w0xT, EE, G4);
        transpose_cvt<<<dim3(NH/32, G4/32), blk>>>(w0 + (size_t)EE*G4, G4, w0hT, NH, G4);
        transpose_cvt<<<dim3(NH/32, G4/32), blk>>>(w1,                 G4, w1xT, NH, G4);
        transpose_cvt<<<dim3(NH/32, G4/32), blk>>>(w1 + (size_t)NH*G4, G4, w1hT, NH, G4);
        transpose_cvt<<<dim3(NH/32, VV/32), blk>>>(outw,               VV, owT,  NH, VV);
    }
    zero_i<<<1, 32>>>(ctr);

    // embs = inputs @ emb
    gemm16<__half><<<dim3(EE/128, TB/128), 256, GEMM_SMEM>>>(inph, VV, embT, embs, EE, nullptr, TB, EE, VV);
    // X = embs @ W0x + b0
    gemm16<float><<<dim3(G4/128, TB/128), 256, GEMM_SMEM>>>(embs, EE, w0xT, X, G4, b0, TB, G4, EE);
    // layer 0 (persistent)
    lstm_layer<<<128, 256, LSTM_SMEM>>>(w0hT, X, H0, ctr);
    // X = H0 @ W1x + b1
    gemm16<float><<<dim3(G4/128, TB/128), 256, GEMM_SMEM>>>(H0, NH, w1xT, X, G4, b1, TB, G4, NH);
    // layer 1 (persistent)
    lstm_layer<<<128, 256, LSTM_SMEM>>>(w1hT, X, H1, ctr + 1);
    // logits = H1 @ out_w + out_b
    gemm16<float><<<dim3(VV/128, TB/128), 256, GEMM_SMEM>>>(H1, NH, owT, out, VV, outb, TB, VV, NH);
}